// round 12
// baseline (speedup 1.0000x reference)
#include <cuda_runtime.h>
#include <cuda_bf16.h>
#include <math.h>

typedef unsigned long long u64;
typedef unsigned u32;

#define BB 64
#define TT 256
#define DD 600
#define HH 512
#define GG 2048
#define LL 9
#define MM (BB*TT)

#define LEN_OFF (MM*LL)
#define LLK_OFF (LEN_OFF + BB)
#define TAG_OFF (LLK_OFF + BB)

// -------- scratch (device globals) --------
__device__ float g_x[(size_t)MM*DD];
__device__ float g_xz[2][(size_t)MM*GG];
__device__ __align__(16) uint2 g_hB[2][TT][BB][HH/2];  // [dir][t][b][u-pair] {bf16x2 hi, bf16x2 mid}
__device__ int g_lens[BB];
__device__ unsigned g_cnt4[4];

__device__ __forceinline__ float sigf(float x){ return 1.f/(1.f+__expf(-x)); }
__device__ __forceinline__ float tanhfast(float x){
    x = fminf(fmaxf(x, -15.f), 15.f);
    float e = __expf(2.f*x);
    return (e-1.f)/(e+1.f);
}
__device__ __forceinline__ unsigned f2tf(float f){
    unsigned r; asm("cvt.rna.tf32.f32 %0,%1;" : "=r"(r) : "f"(f)); return r;
}
__device__ __forceinline__ void mma8(float* d, const unsigned* a, const unsigned* b){
    asm("mma.sync.aligned.m16n8k8.row.col.f32.tf32.tf32.f32 "
        "{%0,%1,%2,%3},{%4,%5,%6,%7},{%8,%9},{%0,%1,%2,%3};"
        : "+f"(d[0]),"+f"(d[1]),"+f"(d[2]),"+f"(d[3])
        : "r"(a[0]),"r"(a[1]),"r"(a[2]),"r"(a[3]),"r"(b[0]),"r"(b[1]));
}
__device__ __forceinline__ void mma16(float* d, const unsigned* a, const unsigned* b){
    asm("mma.sync.aligned.m16n8k16.row.col.f32.bf16.bf16.f32 "
        "{%0,%1,%2,%3},{%4,%5,%6,%7},{%8,%9},{%0,%1,%2,%3};"
        : "+f"(d[0]),"+f"(d[1]),"+f"(d[2]),"+f"(d[3])
        : "r"(a[0]),"r"(a[1]),"r"(a[2]),"r"(a[3]),"r"(b[0]),"r"(b[1]));
}
__device__ __forceinline__ void bfsplit(float w, unsigned short& hi, unsigned short& mid){
    __nv_bfloat16 h = __float2bfloat16_rn(w);
    float r = w - __bfloat162float(h);
    __nv_bfloat16 m = __float2bfloat16_rn(r);
    hi = __bfloat16_as_ushort(h); mid = __bfloat16_as_ushort(m);
}
__device__ __forceinline__ float bflo(u32 v){ return __uint_as_float(v<<16); }
__device__ __forceinline__ float bfhi(u32 v){ return __uint_as_float(v & 0xffff0000u); }

// ---------------- embedding gather (float4) ----------------
__global__ void embed_kernel(const int* __restrict__ text, const int* __restrict__ sent,
                             const float* __restrict__ wemb, const float* __restrict__ semb)
{
    int idx = blockIdx.x*blockDim.x + threadIdx.x;
    if (idx == 0){ g_cnt4[0]=0; g_cnt4[1]=0; g_cnt4[2]=0; g_cnt4[3]=0; }
    if (idx >= MM*150) return;
    int e4 = idx % 150, bt = idx / 150;
    float4 v;
    if (e4 < 75) v = ((const float4*)(wemb + (long)text[bt]*300))[e4];
    else         v = ((const float4*)(semb + (long)sent[bt]*300))[e4-75];
    ((float4*)g_x)[idx] = v;
}

// ---------------- xz = x @ Wk + b  (TF32 mma.sync, double-buffered) ----------------
#define AST 28
#define WST 72
__global__ void __launch_bounds__(256,2) gemm_xz_kernel(const float* __restrict__ Wk_f, const float* __restrict__ b_f,
                                                        const float* __restrict__ Wk_b, const float* __restrict__ b_b)
{
    __shared__ unsigned As[2][128*AST];
    __shared__ unsigned Ws[2][24*WST];

    int tid = threadIdx.x;
    int warp = tid>>5, lane = tid&31;
    int g = lane>>2, tig = lane&3;
    int m0g = blockIdx.x*128;
    int nb  = blockIdx.y;
    const float* Bmat = (nb>=32)? Wk_b : Wk_f;
    const float* bias = (nb>=32)? b_b  : b_f;
    float* C = (nb>=32)? g_xz[1] : g_xz[0];
    int n0g = (nb&31)*64;
    int wm = (warp>>1)*32;
    int wn = (warp&1)*32;

    float acc[2][4][4];
    #pragma unroll
    for (int mt=0;mt<2;mt++)
        #pragma unroll
        for (int nt=0;nt<4;nt++)
            #pragma unroll
            for (int r=0;r<4;r++) acc[mt][nt][r]=0.f;

    int arow = tid>>1, acb = (tid&1)*12;
    int wi0 = tid*2;

    float4 pa[3], pw[2];
    #pragma unroll
    for (int j=0;j<3;j++)
        pa[j] = *(const float4*)&g_x[(long)(m0g+arow)*DD + acb + 4*j];
    if (tid < 192){
        #pragma unroll
        for (int q=0;q<2;q++){
            int i = wi0+q; int k = i>>4, nq = i&15;
            pw[q] = *(const float4*)&Bmat[(long)k*GG + n0g + nq*4];
        }
    }
    #pragma unroll
    for (int j=0;j<3;j++){
        unsigned* d = &As[0][arow*AST + acb + 4*j];
        d[0]=f2tf(pa[j].x); d[1]=f2tf(pa[j].y); d[2]=f2tf(pa[j].z); d[3]=f2tf(pa[j].w);
    }
    if (tid < 192){
        #pragma unroll
        for (int q=0;q<2;q++){
            int i = wi0+q; int k = i>>4, nq = i&15;
            unsigned* d = &Ws[0][k*WST + nq*4];
            d[0]=f2tf(pw[q].x); d[1]=f2tf(pw[q].y); d[2]=f2tf(pw[q].z); d[3]=f2tf(pw[q].w);
        }
    }
    __syncthreads();

    for (int ch=0; ch<25; ch++){
        int cur = ch&1;
        if (ch < 24){
            int kb = (ch+1)*24;
            #pragma unroll
            for (int j=0;j<3;j++)
                pa[j] = *(const float4*)&g_x[(long)(m0g+arow)*DD + kb + acb + 4*j];
            if (tid < 192){
                #pragma unroll
                for (int q=0;q<2;q++){
                    int i = wi0+q; int k = i>>4, nq = i&15;
                    pw[q] = *(const float4*)&Bmat[(long)(kb+k)*GG + n0g + nq*4];
                }
            }
        }
        const unsigned* Ab = &As[cur][0];
        const unsigned* Wb = &Ws[cur][0];
        #pragma unroll
        for (int ks=0;ks<3;ks++){
            int kb = ks*8;
            unsigned a[2][4], b[4][2];
            #pragma unroll
            for (int mt=0;mt<2;mt++){
                int r0 = wm + mt*16;
                a[mt][0] = Ab[(r0+g  )*AST + kb+tig  ];
                a[mt][1] = Ab[(r0+g+8)*AST + kb+tig  ];
                a[mt][2] = Ab[(r0+g  )*AST + kb+tig+4];
                a[mt][3] = Ab[(r0+g+8)*AST + kb+tig+4];
            }
            #pragma unroll
            for (int nt=0;nt<4;nt++){
                int c0 = wn + nt*8 + g;
                b[nt][0] = Wb[(kb+tig  )*WST + c0];
                b[nt][1] = Wb[(kb+tig+4)*WST + c0];
            }
            #pragma unroll
            for (int mt=0;mt<2;mt++)
                #pragma unroll
                for (int nt=0;nt<4;nt++)
                    mma8(acc[mt][nt], a[mt], b[nt]);
        }
        if (ch < 24){
            int nxt = (ch+1)&1;
            #pragma unroll
            for (int j=0;j<3;j++){
                unsigned* d = &As[nxt][arow*AST + acb + 4*j];
                d[0]=f2tf(pa[j].x); d[1]=f2tf(pa[j].y); d[2]=f2tf(pa[j].z); d[3]=f2tf(pa[j].w);
            }
            if (tid < 192){
                #pragma unroll
                for (int q=0;q<2;q++){
                    int i = wi0+q; int k = i>>4, nq = i&15;
                    unsigned* d = &Ws[nxt][k*WST + nq*4];
                    d[0]=f2tf(pw[q].x); d[1]=f2tf(pw[q].y); d[2]=f2tf(pw[q].z); d[3]=f2tf(pw[q].w);
                }
            }
        }
        __syncthreads();
    }

    #pragma unroll
    for (int mt=0;mt<2;mt++){
        int row0 = m0g + wm + mt*16 + g;
        #pragma unroll
        for (int nt=0;nt<4;nt++){
            int col = n0g + wn + nt*8 + 2*tig;
            float b0 = bias[col], b1 = bias[col+1];
            float2 o0 = {acc[mt][nt][0]+b0, acc[mt][nt][1]+b1};
            float2 o1 = {acc[mt][nt][2]+b0, acc[mt][nt][3]+b1};
            *(float2*)&C[(long)row0*GG + col]     = o0;
            *(float2*)&C[(long)(row0+8)*GG + col] = o1;
        }
    }
}

// ---------------- persistent bidirectional LSTM ----------------
// 128 blocks x 256 thr (8 warps, split-K). Block: M=32 batch, N=64 cols, K=512.
// warps 0-3: K 0..255; warps 4-7: K 256..511. Each 128-thr group stages its own
// K-half from g_hB (quarter double-buffered, named barriers). SMEM reduce for split-K.
#define OFF_AH  32768
#define OFF_AM  41088
#define OFF_RB  49408
#define LSTM_SMEM ((49408 + 2176)*4)
__global__ void __launch_bounds__(256,1) lstm_persistent(const float* __restrict__ Wr_f,
                                                         const float* __restrict__ Wr_b)
{
    extern __shared__ u32 sm[];
    uint4* WFs = (uint4*)sm;
    u32*   AHs = sm + OFF_AH;     // [m(32)][kp(256)] stride 260
    u32*   AMs = sm + OFF_AM;
    float* Rbuf= (float*)(sm + OFF_RB);

    int tid = threadIdx.x, bid = blockIdx.x;
    int dir = bid>>6, rr = bid&63, bh = rr>>5, cg = rr&31;
    int b0 = bh*32, u0 = cg*16;
    int grp = dir*2 + bh;
    const float* Wr = dir ? Wr_b : Wr_f;
    const float* xz = g_xz[dir];

    // stage W fragments (once)
    for (int i = tid; i < 8192; i += 256){
        int ntile = i>>10, kt = (i>>5)&31, ln = i&31;
        int q = ntile>>1, uhx = ntile&1, gg = ln>>2, tg = ln&3;
        int col = q*HH + u0 + uhx*8 + gg;
        int p0 = kt*8+tg, p1 = p0+4;
        float w00 = Wr[(long)(2*p0  )*GG + col];
        float w01 = Wr[(long)(2*p0+1)*GG + col];
        float w10 = Wr[(long)(2*p1  )*GG + col];
        float w11 = Wr[(long)(2*p1+1)*GG + col];
        unsigned short h0,m0,h1,m1,h2,m2,h3,m3;
        bfsplit(w00,h0,m0); bfsplit(w01,h1,m1);
        bfsplit(w10,h2,m2); bfsplit(w11,h3,m3);
        uint4 o;
        o.x = ((u32)h1<<16)|h0; o.y = ((u32)h3<<16)|h2;
        o.z = ((u32)m1<<16)|m0; o.w = ((u32)m3<<16)|m2;
        WFs[i] = o;
    }

    int lane = tid&31, w = tid>>5;
    int g = lane>>2, tig = lane&3;
    int khalf = w>>2, wl = w&3;
    int mt = wl>>1, uh = wl&1;
    int wq = uh*1024 + lane;
    int r0 = (mt*16+g)*260, r1 = r0 + 8*260;
    int kt0 = khalf*16;
    int gtid = tid&127;
    int barid = 8 + khalf;
    float cst[4] = {0.f,0.f,0.f,0.f};
    __syncthreads();

    for (int s=0; s<TT; s++){
        int t = dir ? (TT-1-s) : s;

        // xz addends (warps 0-3 only)
        float2 pz[4][2];
        if (tid < 128){
            #pragma unroll
            for (int q=0;q<4;q++)
                #pragma unroll
                for (int bi=0;bi<2;bi++){
                    int brow = b0 + mt*16 + g + bi*8;
                    pz[q][bi] = *(const float2*)&xz[((long)brow*TT + t)*GG + q*HH + u0 + uh*8 + 2*tig];
                }
        }

        float acc[4][4];
        #pragma unroll
        for (int q=0;q<4;q++)
            #pragma unroll
            for (int r=0;r<4;r++) acc[q][r]=0.f;

        if (s){
            int tp = dir ? (t+1) : (t-1);
            const uint4* src = (const uint4*)&g_hB[dir][tp][b0][0];   // 128 uint4 per row
            // quarter 0 of this group's K-half: uint4 cols [khalf*64 .. +32)
            uint4 pf[8];
            #pragma unroll
            for (int j=0;j<8;j++){
                int idx = j*128 + gtid;
                int m = idx>>5, c = idx&31;
                pf[j] = __ldcg(&src[m*128 + khalf*64 + c]);
            }
            #pragma unroll
            for (int j=0;j<8;j++){
                int idx = j*128 + gtid;
                int m = idx>>5, c = idx&31;
                int up = khalf*128 + c*2;
                AHs[m*260 + up  ] = pf[j].x;  AMs[m*260 + up  ] = pf[j].y;
                AHs[m*260 + up+1] = pf[j].z;  AMs[m*260 + up+1] = pf[j].w;
            }
            asm volatile("bar.sync %0, 128;" :: "r"(barid) : "memory");
            // prefetch quarter 1
            #pragma unroll
            for (int j=0;j<8;j++){
                int idx = j*128 + gtid;
                int m = idx>>5, c = idx&31;
                pf[j] = __ldcg(&src[m*128 + khalf*64 + 32 + c]);
            }
            // mma on quarter 0 (kk 0..7)
            #pragma unroll 4
            for (int kk=0; kk<8; kk++){
                int kt = kt0 + kk;
                int kp0 = kt*8+tig, kp1 = kp0+4;
                u32 ah[4], am[4];
                ah[0]=AHs[r0+kp0]; ah[1]=AHs[r1+kp0];
                ah[2]=AHs[r0+kp1]; ah[3]=AHs[r1+kp1];
                am[0]=AMs[r0+kp0]; am[1]=AMs[r1+kp0];
                am[2]=AMs[r0+kp1]; am[3]=AMs[r1+kp1];
                #pragma unroll
                for (int q=0;q<4;q++){
                    uint4 wv = WFs[q*2048 + kt*32 + wq];
                    u32 bh_[2] = {wv.x, wv.y};
                    u32 bm_[2] = {wv.z, wv.w};
                    mma16(acc[q], ah, bh_);
                    mma16(acc[q], ah, bm_);
                    mma16(acc[q], am, bh_);
                }
            }
            // store quarter 1
            #pragma unroll
            for (int j=0;j<8;j++){
                int idx = j*128 + gtid;
                int m = idx>>5, c = idx&31;
                int up = khalf*128 + 64 + c*2;
                AHs[m*260 + up  ] = pf[j].x;  AMs[m*260 + up  ] = pf[j].y;
                AHs[m*260 + up+1] = pf[j].z;  AMs[m*260 + up+1] = pf[j].w;
            }
            asm volatile("bar.sync %0, 128;" :: "r"(barid) : "memory");
            // mma on quarter 1 (kk 8..15)
            #pragma unroll 4
            for (int kk=8; kk<16; kk++){
                int kt = kt0 + kk;
                int kp0 = kt*8+tig, kp1 = kp0+4;
                u32 ah[4], am[4];
                ah[0]=AHs[r0+kp0]; ah[1]=AHs[r1+kp0];
                ah[2]=AHs[r0+kp1]; ah[3]=AHs[r1+kp1];
                am[0]=AMs[r0+kp0]; am[1]=AMs[r1+kp0];
                am[2]=AMs[r0+kp1]; am[3]=AMs[r1+kp1];
                #pragma unroll
                for (int q=0;q<4;q++){
                    uint4 wv = WFs[q*2048 + kt*32 + wq];
                    u32 bh_[2] = {wv.x, wv.y};
                    u32 bm_[2] = {wv.z, wv.w};
                    mma16(acc[q], ah, bh_);
                    mma16(acc[q], ah, bm_);
                    mma16(acc[q], am, bh_);
                }
            }

            // split-K reduce: warps 4-7 -> SMEM -> warps 0-3
            if (tid >= 128){
                float* rb = &Rbuf[(tid-128)*17];
                #pragma unroll
                for (int q=0;q<4;q++)
                    #pragma unroll
                    for (int r=0;r<4;r++) rb[q*4+r] = acc[q][r];
            }
            __syncthreads();
            if (tid < 128){
                const float* rb = &Rbuf[tid*17];
                #pragma unroll
                for (int q=0;q<4;q++)
                    #pragma unroll
                    for (int r=0;r<4;r++) acc[q][r] += rb[q*4+r];
            }
        }

        // gates + state update (warps 0-3)
        if (tid < 128){
            #pragma unroll
            for (int bi=0;bi<2;bi++){
                int brow = b0 + mt*16 + g + bi*8;
                float zi0 = acc[0][bi*2  ] + pz[0][bi].x;
                float zi1 = acc[0][bi*2+1] + pz[0][bi].y;
                float zf0 = acc[1][bi*2  ] + pz[1][bi].x;
                float zf1 = acc[1][bi*2+1] + pz[1][bi].y;
                float zg0 = acc[2][bi*2  ] + pz[2][bi].x;
                float zg1 = acc[2][bi*2+1] + pz[2][bi].y;
                float zo0 = acc[3][bi*2  ] + pz[3][bi].x;
                float zo1 = acc[3][bi*2+1] + pz[3][bi].y;
                float cn0 = sigf(zf0)*cst[bi*2  ] + sigf(zi0)*tanhfast(zg0);
                float cn1 = sigf(zf1)*cst[bi*2+1] + sigf(zi1)*tanhfast(zg1);
                cst[bi*2  ] = cn0; cst[bi*2+1] = cn1;
                float h0 = sigf(zo0)*tanhfast(cn0);
                float h1 = sigf(zo1)*tanhfast(cn1);
                unsigned short hh0,hm0,hh1,hm1;
                bfsplit(h0,hh0,hm0); bfsplit(h1,hh1,hm1);
                int up = cg*8 + uh*4 + tig;
                uint2 pk;
                pk.x = ((u32)hh1<<16) | hh0;
                pk.y = ((u32)hm1<<16) | hm0;
                g_hB[dir][t][brow][up] = pk;
            }
        }

        if (s < TT-1){
            __threadfence();
            __syncthreads();
            if (tid==0){
                atomicAdd(&g_cnt4[grp], 1u);
                unsigned tgt = 32u*(unsigned)(s+1);
                while (*(volatile unsigned*)&g_cnt4[grp] < tgt) __nanosleep(16);
            }
            __syncthreads();
        }
    }
}

// ---------------- logits = [hf|hb] @ Wd + bd ----------------
// grid 256 (t), block 512 (16 warps); warp handles 4 b-rows; reads packed g_hB.
__global__ void __launch_bounds__(512) logits_kernel(const float* __restrict__ Wd, const float* __restrict__ bd,
                                                     float* __restrict__ out)
{
    __shared__ float sW[1024*LL];
    int t = blockIdx.x, tid = threadIdx.x;
    for (int i=tid; i<1024*LL; i+=512) sW[i] = Wd[i];
    __syncthreads();

    int warp = tid>>5, lane = tid&31;
    int b0 = warp*4;
    float acc[4][LL];
    #pragma unroll
    for (int r=0;r<4;r++)
        #pragma unroll
        for (int l=0;l<LL;l++) acc[r][l]=0.f;

    #pragma unroll
    for (int it=0; it<8; it++){
        int dirsel = it>>2;
        int uc = (it&3)*128 + lane*4;       // unit base (4 units)
        int c4 = (it&3)*32 + lane;          // uint4 index within row
        float4 v[4];
        #pragma unroll
        for (int r=0;r<4;r++){
            uint4 p = *(const uint4*)((const u32*)&g_hB[dirsel][t][b0+r][0] + c4*4);
            v[r].x = bflo(p.x) + bflo(p.y);
            v[r].y = bfhi(p.x) + bfhi(p.y);
            v[r].z = bflo(p.z) + bflo(p.w);
            v[r].w = bfhi(p.z) + bfhi(p.w);
        }
        int wbase = (dirsel*HH + uc)*LL;
        #pragma unroll
        for (int e=0;e<4;e++){
            float w9[LL];
            #pragma unroll
            for (int l=0;l<LL;l++) w9[l] = sW[wbase + e*LL + l];
            #pragma unroll
            for (int r=0;r<4;r++){
                float hv = (e==0)?v[r].x:(e==1)?v[r].y:(e==2)?v[r].z:v[r].w;
                #pragma unroll
                for (int l=0;l<LL;l++) acc[r][l] += hv*w9[l];
            }
        }
    }
    #pragma unroll
    for (int r=0;r<4;r++)
        #pragma unroll
        for (int l=0;l<LL;l++){
            float v = acc[r][l];
            #pragma unroll
            for (int off=16;off;off>>=1) v += __shfl_down_sync(0xffffffffu, v, off);
            acc[r][l] = v;
        }
    if (lane==0){
        #pragma unroll
        for (int r=0;r<4;r++)
            #pragma unroll
            for (int l=0;l<LL;l++)
                out[((long)(b0+r)*TT + t)*LL + l] = acc[r][l] + bd[l];
    }
}

// ---------------- text lens ----------------
__global__ void lens_kernel(const int* __restrict__ text, float* __restrict__ outlen)
{
    __shared__ int sred[TT];
    int b = blockIdx.x, tid = threadIdx.x;
    sred[tid] = (text[b*TT+tid] != 0) ? 1 : 0;
    __syncthreads();
    for (int s=TT/2; s; s>>=1){
        if (tid < s) sred[tid] += sred[tid+s];
        __syncthreads();
    }
    if (tid==0){ g_lens[b] = sred[0]; outlen[b] = (float)sred[0]; }
}

// ---------------- fused CRF log-likelihood + Viterbi ----------------
__global__ void crf_kernel(const float* __restrict__ logits, const int* __restrict__ labels,
                           const float* __restrict__ trans, float* __restrict__ outll,
                           float* __restrict__ outtags)
{
    int b = blockIdx.x, lane = threadIdx.x;
    __shared__ float tr[LL*LL];
    __shared__ unsigned char bp[TT-1][LL];
    for (int i=lane;i<LL*LL;i+=32) tr[i]=trans[i];
    __syncwarp();
    int len = g_lens[b];
    const float* lg = logits + (long)b*TT*LL;
    const int* lab = labels + b*TT;

    float un=0.f, bi=0.f;
    for (int t=lane;t<TT;t+=32){
        if (t < len)           un += lg[t*LL + lab[t]];
        if (t >= 1 && t < len) bi += tr[lab[t-1]*LL + lab[t]];
    }
    #pragma unroll
    for (int off=16;off;off>>=1){
        un += __shfl_down_sync(0xffffffffu, un, off);
        bi += __shfl_down_sync(0xffffffffu, bi, off);
    }

    int j = (lane<LL)? lane : 0;
    float aL = (lane<LL)? lg[lane] : -1e30f;
    float aV = aL;
    for (int t=1;t<TT;t++){
        float lt = (lane<LL)? lg[t*LL+lane] : 0.f;
        float av[LL]; float mxL = -1e30f;
        float bestV = -1e30f; int bidx = 0;
        #pragma unroll
        for (int i=0;i<LL;i++){
            float aLi = __shfl_sync(0xffffffffu, aL, i);
            float aVi = __shfl_sync(0xffffffffu, aV, i);
            float trij = tr[i*LL + j];
            av[i] = aLi + trij;
            mxL = fmaxf(mxL, av[i]);
            float vV = aVi + trij;
            if (vV > bestV){ bestV = vV; bidx = i; }
        }
        float ssum = 0.f;
        #pragma unroll
        for (int i=0;i<LL;i++) ssum += __expf(av[i]-mxL);
        float nwL = __logf(ssum) + mxL + lt;
        bool m = (t < len);
        if (lane<LL){
            if (m){ aL = nwL; aV = bestV + lt; }
            bp[t-1][lane] = m ? (unsigned char)bidx : (unsigned char)lane;
        }
    }
    float mx2 = -1e30f;
    #pragma unroll
    for (int i=0;i<LL;i++) mx2 = fmaxf(mx2, __shfl_sync(0xffffffffu, aL, i));
    float s2 = 0.f;
    #pragma unroll
    for (int i=0;i<LL;i++) s2 += __expf(__shfl_sync(0xffffffffu, aL, i) - mx2);
    float log_norm = __logf(s2) + mx2;
    int last = 0; float bv = -1e30f;
    #pragma unroll
    for (int i=0;i<LL;i++){
        float v = __shfl_sync(0xffffffffu, aV, i);
        if (v > bv){ bv = v; last = i; }
    }
    if (lane==0){
        outll[b] = un + bi - log_norm;
        int tag = last;
        outtags[b*TT + TT-1] = (float)tag;
        for (int t=TT-2;t>=0;t--){
            tag = bp[t][tag];
            outtags[b*TT + t] = (float)tag;
        }
    }
}

// ---------------- launch ----------------
extern "C" void kernel_launch(void* const* d_in, const int* in_sizes, int n_in,
                              void* d_out, int out_size)
{
    const int*   text  = (const int*)  d_in[0];
    const int*   sent  = (const int*)  d_in[1];
    const int*   labels= (const int*)  d_in[2];
    const float* wemb  = (const float*)d_in[3];
    const float* semb  = (const float*)d_in[4];
    const float* Wk_f  = (const float*)d_in[5];
    const float* Wr_f  = (const float*)d_in[6];
    const float* b_f   = (const float*)d_in[7];
    const float* Wk_b  = (const float*)d_in[8];
    const float* Wr_b  = (const float*)d_in[9];
    const float* b_b   = (const float*)d_in[10];
    const float* Wd    = (const float*)d_in[11];
    const float* bd    = (const float*)d_in[12];
    const float* trans = (const float*)d_in[13];
    float* out = (float*)d_out;

    cudaFuncSetAttribute(lstm_persistent, cudaFuncAttributeMaxDynamicSharedMemorySize, LSTM_SMEM);

    embed_kernel<<<(MM*150 + 255)/256, 256>>>(text, sent, wemb, semb);
    gemm_xz_kernel<<<dim3(128, 64), 256>>>(Wk_f, b_f, Wk_b, b_b);
    lstm_persistent<<<128, 256, LSTM_SMEM>>>(Wr_f, Wr_b);
    logits_kernel<<<256, 512>>>(Wd, bd, out);
    lens_kernel<<<BB, TT>>>(text, out + LEN_OFF);
    crf_kernel<<<BB, 32>>>(out, labels, trans, out + LLK_OFF, out + TAG_OFF);
}

// round 13
// speedup vs baseline: 1.0024x; 1.0024x over previous
#include <cuda_runtime.h>
#include <cuda_bf16.h>
#include <math.h>

typedef unsigned long long u64;
typedef unsigned u32;

#define BB 64
#define TT 256
#define DD 600
#define HH 512
#define GG 2048
#define LL 9
#define MM (BB*TT)

#define LEN_OFF (MM*LL)
#define LLK_OFF (LEN_OFF + BB)
#define TAG_OFF (LLK_OFF + BB)

// -------- scratch (device globals) --------
__device__ float g_x[(size_t)MM*DD];
__device__ float g_xz[2][(size_t)MM*GG];
__device__ __align__(16) uint2 g_hB[2][TT][BB][HH/2];  // [dir][t][b][u-pair] {bf16x2 hi, bf16x2 mid}
__device__ int g_lens[BB];
__device__ u32 g_flag[2][2][32][32];                   // [dir][bh][cg][pad] - 128B per flag

__device__ __forceinline__ float sigf(float x){ return 1.f/(1.f+__expf(-x)); }
__device__ __forceinline__ float tanhfast(float x){
    x = fminf(fmaxf(x, -15.f), 15.f);
    float e = __expf(2.f*x);
    return (e-1.f)/(e+1.f);
}
__device__ __forceinline__ unsigned f2tf(float f){
    unsigned r; asm("cvt.rna.tf32.f32 %0,%1;" : "=r"(r) : "f"(f)); return r;
}
__device__ __forceinline__ void mma8(float* d, const unsigned* a, const unsigned* b){
    asm("mma.sync.aligned.m16n8k8.row.col.f32.tf32.tf32.f32 "
        "{%0,%1,%2,%3},{%4,%5,%6,%7},{%8,%9},{%0,%1,%2,%3};"
        : "+f"(d[0]),"+f"(d[1]),"+f"(d[2]),"+f"(d[3])
        : "r"(a[0]),"r"(a[1]),"r"(a[2]),"r"(a[3]),"r"(b[0]),"r"(b[1]));
}
__device__ __forceinline__ void mma16(float* d, const unsigned* a, const unsigned* b){
    asm("mma.sync.aligned.m16n8k16.row.col.f32.bf16.bf16.f32 "
        "{%0,%1,%2,%3},{%4,%5,%6,%7},{%8,%9},{%0,%1,%2,%3};"
        : "+f"(d[0]),"+f"(d[1]),"+f"(d[2]),"+f"(d[3])
        : "r"(a[0]),"r"(a[1]),"r"(a[2]),"r"(a[3]),"r"(b[0]),"r"(b[1]));
}
__device__ __forceinline__ void bfsplit(float w, unsigned short& hi, unsigned short& mid){
    __nv_bfloat16 h = __float2bfloat16_rn(w);
    float r = w - __bfloat162float(h);
    __nv_bfloat16 m = __float2bfloat16_rn(r);
    hi = __bfloat16_as_ushort(h); mid = __bfloat16_as_ushort(m);
}
__device__ __forceinline__ float bflo(u32 v){ return __uint_as_float(v<<16); }
__device__ __forceinline__ float bfhi(u32 v){ return __uint_as_float(v & 0xffff0000u); }

// ---------------- embedding gather (float4) + flag reset ----------------
__global__ void embed_kernel(const int* __restrict__ text, const int* __restrict__ sent,
                             const float* __restrict__ wemb, const float* __restrict__ semb)
{
    int idx = blockIdx.x*blockDim.x + threadIdx.x;
    if (idx < 4096) ((u32*)g_flag)[idx] = 0;
    if (idx >= MM*150) return;
    int e4 = idx % 150, bt = idx / 150;
    float4 v;
    if (e4 < 75) v = ((const float4*)(wemb + (long)text[bt]*300))[e4];
    else         v = ((const float4*)(semb + (long)sent[bt]*300))[e4-75];
    ((float4*)g_x)[idx] = v;
}

// ---------------- xz = x @ Wk + b  (TF32 mma.sync, double-buffered) ----------------
#define AST 28
#define WST 72
__global__ void __launch_bounds__(256,2) gemm_xz_kernel(const float* __restrict__ Wk_f, const float* __restrict__ b_f,
                                                        const float* __restrict__ Wk_b, const float* __restrict__ b_b)
{
    __shared__ unsigned As[2][128*AST];
    __shared__ unsigned Ws[2][24*WST];

    int tid = threadIdx.x;
    int warp = tid>>5, lane = tid&31;
    int g = lane>>2, tig = lane&3;
    int m0g = blockIdx.x*128;
    int nb  = blockIdx.y;
    const float* Bmat = (nb>=32)? Wk_b : Wk_f;
    const float* bias = (nb>=32)? b_b  : b_f;
    float* C = (nb>=32)? g_xz[1] : g_xz[0];
    int n0g = (nb&31)*64;
    int wm = (warp>>1)*32;
    int wn = (warp&1)*32;

    float acc[2][4][4];
    #pragma unroll
    for (int mt=0;mt<2;mt++)
        #pragma unroll
        for (int nt=0;nt<4;nt++)
            #pragma unroll
            for (int r=0;r<4;r++) acc[mt][nt][r]=0.f;

    int arow = tid>>1, acb = (tid&1)*12;
    int wi0 = tid*2;

    float4 pa[3], pw[2];
    #pragma unroll
    for (int j=0;j<3;j++)
        pa[j] = *(const float4*)&g_x[(long)(m0g+arow)*DD + acb + 4*j];
    if (tid < 192){
        #pragma unroll
        for (int q=0;q<2;q++){
            int i = wi0+q; int k = i>>4, nq = i&15;
            pw[q] = *(const float4*)&Bmat[(long)k*GG + n0g + nq*4];
        }
    }
    #pragma unroll
    for (int j=0;j<3;j++){
        unsigned* d = &As[0][arow*AST + acb + 4*j];
        d[0]=f2tf(pa[j].x); d[1]=f2tf(pa[j].y); d[2]=f2tf(pa[j].z); d[3]=f2tf(pa[j].w);
    }
    if (tid < 192){
        #pragma unroll
        for (int q=0;q<2;q++){
            int i = wi0+q; int k = i>>4, nq = i&15;
            unsigned* d = &Ws[0][k*WST + nq*4];
            d[0]=f2tf(pw[q].x); d[1]=f2tf(pw[q].y); d[2]=f2tf(pw[q].z); d[3]=f2tf(pw[q].w);
        }
    }
    __syncthreads();

    for (int ch=0; ch<25; ch++){
        int cur = ch&1;
        if (ch < 24){
            int kb = (ch+1)*24;
            #pragma unroll
            for (int j=0;j<3;j++)
                pa[j] = *(const float4*)&g_x[(long)(m0g+arow)*DD + kb + acb + 4*j];
            if (tid < 192){
                #pragma unroll
                for (int q=0;q<2;q++){
                    int i = wi0+q; int k = i>>4, nq = i&15;
                    pw[q] = *(const float4*)&Bmat[(long)(kb+k)*GG + n0g + nq*4];
                }
            }
        }
        const unsigned* Ab = &As[cur][0];
        const unsigned* Wb = &Ws[cur][0];
        #pragma unroll
        for (int ks=0;ks<3;ks++){
            int kb = ks*8;
            unsigned a[2][4], b[4][2];
            #pragma unroll
            for (int mt=0;mt<2;mt++){
                int r0 = wm + mt*16;
                a[mt][0] = Ab[(r0+g  )*AST + kb+tig  ];
                a[mt][1] = Ab[(r0+g+8)*AST + kb+tig  ];
                a[mt][2] = Ab[(r0+g  )*AST + kb+tig+4];
                a[mt][3] = Ab[(r0+g+8)*AST + kb+tig+4];
            }
            #pragma unroll
            for (int nt=0;nt<4;nt++){
                int c0 = wn + nt*8 + g;
                b[nt][0] = Wb[(kb+tig  )*WST + c0];
                b[nt][1] = Wb[(kb+tig+4)*WST + c0];
            }
            #pragma unroll
            for (int mt=0;mt<2;mt++)
                #pragma unroll
                for (int nt=0;nt<4;nt++)
                    mma8(acc[mt][nt], a[mt], b[nt]);
        }
        if (ch < 24){
            int nxt = (ch+1)&1;
            #pragma unroll
            for (int j=0;j<3;j++){
                unsigned* d = &As[nxt][arow*AST + acb + 4*j];
                d[0]=f2tf(pa[j].x); d[1]=f2tf(pa[j].y); d[2]=f2tf(pa[j].z); d[3]=f2tf(pa[j].w);
            }
            if (tid < 192){
                #pragma unroll
                for (int q=0;q<2;q++){
                    int i = wi0+q; int k = i>>4, nq = i&15;
                    unsigned* d = &Ws[nxt][k*WST + nq*4];
                    d[0]=f2tf(pw[q].x); d[1]=f2tf(pw[q].y); d[2]=f2tf(pw[q].z); d[3]=f2tf(pw[q].w);
                }
            }
        }
        __syncthreads();
    }

    #pragma unroll
    for (int mt=0;mt<2;mt++){
        int row0 = m0g + wm + mt*16 + g;
        #pragma unroll
        for (int nt=0;nt<4;nt++){
            int col = n0g + wn + nt*8 + 2*tig;
            float b0 = bias[col], b1 = bias[col+1];
            float2 o0 = {acc[mt][nt][0]+b0, acc[mt][nt][1]+b1};
            float2 o1 = {acc[mt][nt][2]+b0, acc[mt][nt][3]+b1};
            *(float2*)&C[(long)row0*GG + col]     = o0;
            *(float2*)&C[(long)(row0+8)*GG + col] = o1;
        }
    }
}

// ---------------- persistent bidirectional LSTM ----------------
// 128 blocks x 256 thr (8 warps, split-K). Block: M=32 batch, N=64 cols, K=512.
// Sync: per-producer release flags; each 128-thr half-group waits only on its
// 16 producer flags (parallel ld.acquire poll), no atomics, no global counter.
#define OFF_AH  32768
#define OFF_AM  41088
#define OFF_RB  49408
#define LSTM_SMEM ((49408 + 2*2176)*4)
__global__ void __launch_bounds__(256,1) lstm_persistent(const float* __restrict__ Wr_f,
                                                         const float* __restrict__ Wr_b)
{
    extern __shared__ u32 sm[];
    uint4* WFs = (uint4*)sm;
    u32*   AHs = sm + OFF_AH;     // [m(32)][kp(256)] stride 260
    u32*   AMs = sm + OFF_AM;
    float* Rbuf= (float*)(sm + OFF_RB);   // 2 x 2176 (step parity)

    int tid = threadIdx.x, bid = blockIdx.x;
    int dir = bid>>6, rr = bid&63, bh = rr>>5, cg = rr&31;
    int b0 = bh*32, u0 = cg*16;
    const float* Wr = dir ? Wr_b : Wr_f;
    const float* xz = g_xz[dir];

    // stage W fragments (once)
    for (int i = tid; i < 8192; i += 256){
        int ntile = i>>10, kt = (i>>5)&31, ln = i&31;
        int q = ntile>>1, uhx = ntile&1, gg = ln>>2, tg = ln&3;
        int col = q*HH + u0 + uhx*8 + gg;
        int p0 = kt*8+tg, p1 = p0+4;
        float w00 = Wr[(long)(2*p0  )*GG + col];
        float w01 = Wr[(long)(2*p0+1)*GG + col];
        float w10 = Wr[(long)(2*p1  )*GG + col];
        float w11 = Wr[(long)(2*p1+1)*GG + col];
        unsigned short h0,m0,h1,m1,h2,m2,h3,m3;
        bfsplit(w00,h0,m0); bfsplit(w01,h1,m1);
        bfsplit(w10,h2,m2); bfsplit(w11,h3,m3);
        uint4 o;
        o.x = ((u32)h1<<16)|h0; o.y = ((u32)h3<<16)|h2;
        o.z = ((u32)m1<<16)|m0; o.w = ((u32)m3<<16)|m2;
        WFs[i] = o;
    }

    int lane = tid&31, w = tid>>5;
    int g = lane>>2, tig = lane&3;
    int khalf = w>>2, wl = w&3;
    int mt = wl>>1, uh = wl&1;
    int wq = uh*1024 + lane;
    int r0 = (mt*16+g)*260, r1 = r0 + 8*260;
    int kt0 = khalf*16;
    int gtid = tid&127;
    int barid = 8 + khalf;
    float cst[4] = {0.f,0.f,0.f,0.f};
    __syncthreads();

    for (int s=0; s<TT; s++){
        int t = dir ? (TT-1-s) : s;

        // xz addends (warps 0-3 only) - issued before any waiting
        float2 pz[4][2];
        if (tid < 128){
            #pragma unroll
            for (int q=0;q<4;q++)
                #pragma unroll
                for (int bi=0;bi<2;bi++){
                    int brow = b0 + mt*16 + g + bi*8;
                    pz[q][bi] = *(const float2*)&xz[((long)brow*TT + t)*GG + q*HH + u0 + uh*8 + 2*tig];
                }
        }

        float acc[4][4];
        #pragma unroll
        for (int q=0;q<4;q++)
            #pragma unroll
            for (int r=0;r<4;r++) acc[q][r]=0.f;

        if (s){
            // wait for the 16 producers this half-group needs (parallel poll)
            if (wl == 0){
                if (lane < 16){
                    const u32* fp = &g_flag[dir][bh][khalf*16 + lane][0];
                    u32 v;
                    while (1){
                        asm volatile("ld.acquire.gpu.global.u32 %0,[%1];" : "=r"(v) : "l"(fp) : "memory");
                        if (v >= (u32)s) break;
                        __nanosleep(20);
                    }
                }
                __syncwarp();
            }
            asm volatile("bar.sync %0, 128;" :: "r"(barid) : "memory");

            int tp = dir ? (t+1) : (t-1);
            const uint4* src = (const uint4*)&g_hB[dir][tp][b0][0];   // 128 uint4 per row
            uint4 pf[8];
            #pragma unroll
            for (int j=0;j<8;j++){
                int idx = j*128 + gtid;
                int m = idx>>5, c = idx&31;
                pf[j] = __ldcg(&src[m*128 + khalf*64 + c]);
            }
            #pragma unroll
            for (int j=0;j<8;j++){
                int idx = j*128 + gtid;
                int m = idx>>5, c = idx&31;
                int up = khalf*128 + c*2;
                AHs[m*260 + up  ] = pf[j].x;  AMs[m*260 + up  ] = pf[j].y;
                AHs[m*260 + up+1] = pf[j].z;  AMs[m*260 + up+1] = pf[j].w;
            }
            asm volatile("bar.sync %0, 128;" :: "r"(barid) : "memory");
            // prefetch quarter 1
            #pragma unroll
            for (int j=0;j<8;j++){
                int idx = j*128 + gtid;
                int m = idx>>5, c = idx&31;
                pf[j] = __ldcg(&src[m*128 + khalf*64 + 32 + c]);
            }
            // mma on quarter 0
            #pragma unroll 4
            for (int kk=0; kk<8; kk++){
                int kt = kt0 + kk;
                int kp0 = kt*8+tig, kp1 = kp0+4;
                u32 ah[4], am[4];
                ah[0]=AHs[r0+kp0]; ah[1]=AHs[r1+kp0];
                ah[2]=AHs[r0+kp1]; ah[3]=AHs[r1+kp1];
                am[0]=AMs[r0+kp0]; am[1]=AMs[r1+kp0];
                am[2]=AMs[r0+kp1]; am[3]=AMs[r1+kp1];
                #pragma unroll
                for (int q=0;q<4;q++){
                    uint4 wv = WFs[q*2048 + kt*32 + wq];
                    u32 bh_[2] = {wv.x, wv.y};
                    u32 bm_[2] = {wv.z, wv.w};
                    mma16(acc[q], ah, bh_);
                    mma16(acc[q], ah, bm_);
                    mma16(acc[q], am, bh_);
                }
            }
            // store quarter 1
            #pragma unroll
            for (int j=0;j<8;j++){
                int idx = j*128 + gtid;
                int m = idx>>5, c = idx&31;
                int up = khalf*128 + 64 + c*2;
                AHs[m*260 + up  ] = pf[j].x;  AMs[m*260 + up  ] = pf[j].y;
                AHs[m*260 + up+1] = pf[j].z;  AMs[m*260 + up+1] = pf[j].w;
            }
            asm volatile("bar.sync %0, 128;" :: "r"(barid) : "memory");
            // mma on quarter 1
            #pragma unroll 4
            for (int kk=8; kk<16; kk++){
                int kt = kt0 + kk;
                int kp0 = kt*8+tig, kp1 = kp0+4;
                u32 ah[4], am[4];
                ah[0]=AHs[r0+kp0]; ah[1]=AHs[r1+kp0];
                ah[2]=AHs[r0+kp1]; ah[3]=AHs[r1+kp1];
                am[0]=AMs[r0+kp0]; am[1]=AMs[r1+kp0];
                am[2]=AMs[r0+kp1]; am[3]=AMs[r1+kp1];
                #pragma unroll
                for (int q=0;q<4;q++){
                    uint4 wv = WFs[q*2048 + kt*32 + wq];
                    u32 bh_[2] = {wv.x, wv.y};
                    u32 bm_[2] = {wv.z, wv.w};
                    mma16(acc[q], ah, bh_);
                    mma16(acc[q], ah, bm_);
                    mma16(acc[q], am, bh_);
                }
            }

            // split-K reduce (parity-buffered): warps 4-7 -> SMEM -> warps 0-3
            float* RB = Rbuf + (s&1)*2176;
            if (tid >= 128){
                float* rb = &RB[(tid-128)*17];
                #pragma unroll
                for (int q=0;q<4;q++)
                    #pragma unroll
                    for (int r=0;r<4;r++) rb[q*4+r] = acc[q][r];
            }
            __syncthreads();
            if (tid < 128){
                const float* rb = &RB[tid*17];
                #pragma unroll
                for (int q=0;q<4;q++)
                    #pragma unroll
                    for (int r=0;r<4;r++) acc[q][r] += rb[q*4+r];
            }
        }

        // gates + state update + publish (warps 0-3)
        if (tid < 128){
            #pragma unroll
            for (int bi=0;bi<2;bi++){
                int brow = b0 + mt*16 + g + bi*8;
                float zi0 = acc[0][bi*2  ] + pz[0][bi].x;
                float zi1 = acc[0][bi*2+1] + pz[0][bi].y;
                float zf0 = acc[1][bi*2  ] + pz[1][bi].x;
                float zf1 = acc[1][bi*2+1] + pz[1][bi].y;
                float zg0 = acc[2][bi*2  ] + pz[2][bi].x;
                float zg1 = acc[2][bi*2+1] + pz[2][bi].y;
                float zo0 = acc[3][bi*2  ] + pz[3][bi].x;
                float zo1 = acc[3][bi*2+1] + pz[3][bi].y;
                float cn0 = sigf(zf0)*cst[bi*2  ] + sigf(zi0)*tanhfast(zg0);
                float cn1 = sigf(zf1)*cst[bi*2+1] + sigf(zi1)*tanhfast(zg1);
                cst[bi*2  ] = cn0; cst[bi*2+1] = cn1;
                float h0 = sigf(zo0)*tanhfast(cn0);
                float h1 = sigf(zo1)*tanhfast(cn1);
                unsigned short hh0,hm0,hh1,hm1;
                bfsplit(h0,hh0,hm0); bfsplit(h1,hh1,hm1);
                int up = cg*8 + uh*4 + tig;
                uint2 pk;
                pk.x = ((u32)hh1<<16) | hh0;
                pk.y = ((u32)hm1<<16) | hm0;
                g_hB[dir][t][brow][up] = pk;
            }
            __threadfence();
            asm volatile("bar.sync 8, 128;" ::: "memory");
            if (tid == 0){
                asm volatile("st.release.gpu.global.u32 [%0],%1;"
                             :: "l"(&g_flag[dir][bh][cg][0]), "r"((u32)(s+1)) : "memory");
            }
        }
    }
}

// ---------------- logits = [hf|hb] @ Wd + bd ----------------
__global__ void __launch_bounds__(512) logits_kernel(const float* __restrict__ Wd, const float* __restrict__ bd,
                                                     float* __restrict__ out)
{
    __shared__ float sW[1024*LL];
    int t = blockIdx.x, tid = threadIdx.x;
    for (int i=tid; i<1024*LL; i+=512) sW[i] = Wd[i];
    __syncthreads();

    int warp = tid>>5, lane = tid&31;
    int b0 = warp*4;
    float acc[4][LL];
    #pragma unroll
    for (int r=0;r<4;r++)
        #pragma unroll
        for (int l=0;l<LL;l++) acc[r][l]=0.f;

    #pragma unroll
    for (int it=0; it<8; it++){
        int dirsel = it>>2;
        int uc = (it&3)*128 + lane*4;
        int c4 = (it&3)*32 + lane;
        float4 v[4];
        #pragma unroll
        for (int r=0;r<4;r++){
            uint4 p = *(const uint4*)((const u32*)&g_hB[dirsel][t][b0+r][0] + c4*4);
            v[r].x = bflo(p.x) + bflo(p.y);
            v[r].y = bfhi(p.x) + bfhi(p.y);
            v[r].z = bflo(p.z) + bflo(p.w);
            v[r].w = bfhi(p.z) + bfhi(p.w);
        }
        int wbase = (dirsel*HH + uc)*LL;
        #pragma unroll
        for (int e=0;e<4;e++){
            float w9[LL];
            #pragma unroll
            for (int l=0;l<LL;l++) w9[l] = sW[wbase + e*LL + l];
            #pragma unroll
            for (int r=0;r<4;r++){
                float hv = (e==0)?v[r].x:(e==1)?v[r].y:(e==2)?v[r].z:v[r].w;
                #pragma unroll
                for (int l=0;l<LL;l++) acc[r][l] += hv*w9[l];
            }
        }
    }
    #pragma unroll
    for (int r=0;r<4;r++)
        #pragma unroll
        for (int l=0;l<LL;l++){
            float v = acc[r][l];
            #pragma unroll
            for (int off=16;off;off>>=1) v += __shfl_down_sync(0xffffffffu, v, off);
            acc[r][l] = v;
        }
    if (lane==0){
        #pragma unroll
        for (int r=0;r<4;r++)
            #pragma unroll
            for (int l=0;l<LL;l++)
                out[((long)(b0+r)*TT + t)*LL + l] = acc[r][l] + bd[l];
    }
}

// ---------------- text lens ----------------
__global__ void lens_kernel(const int* __restrict__ text, float* __restrict__ outlen)
{
    __shared__ int sred[TT];
    int b = blockIdx.x, tid = threadIdx.x;
    sred[tid] = (text[b*TT+tid] != 0) ? 1 : 0;
    __syncthreads();
    for (int s=TT/2; s; s>>=1){
        if (tid < s) sred[tid] += sred[tid+s];
        __syncthreads();
    }
    if (tid==0){ g_lens[b] = sred[0]; outlen[b] = (float)sred[0]; }
}

// ---------------- fused CRF log-likelihood + Viterbi ----------------
__global__ void crf_kernel(const float* __restrict__ logits, const int* __restrict__ labels,
                           const float* __restrict__ trans, float* __restrict__ outll,
                           float* __restrict__ outtags)
{
    int b = blockIdx.x, lane = threadIdx.x;
    __shared__ float tr[LL*LL];
    __shared__ unsigned char bp[TT-1][LL];
    for (int i=lane;i<LL*LL;i+=32) tr[i]=trans[i];
    __syncwarp();
    int len = g_lens[b];
    const float* lg = logits + (long)b*TT*LL;
    const int* lab = labels + b*TT;

    float un=0.f, bi=0.f;
    for (int t=lane;t<TT;t+=32){
        if (t < len)           un += lg[t*LL + lab[t]];
        if (t >= 1 && t < len) bi += tr[lab[t-1]*LL + lab[t]];
    }
    #pragma unroll
    for (int off=16;off;off>>=1){
        un += __shfl_down_sync(0xffffffffu, un, off);
        bi += __shfl_down_sync(0xffffffffu, bi, off);
    }

    int j = (lane<LL)? lane : 0;
    float aL = (lane<LL)? lg[lane] : -1e30f;
    float aV = aL;
    for (int t=1;t<TT;t++){
        float lt = (lane<LL)? lg[t*LL+lane] : 0.f;
        float av[LL]; float mxL = -1e30f;
        float bestV = -1e30f; int bidx = 0;
        #pragma unroll
        for (int i=0;i<LL;i++){
            float aLi = __shfl_sync(0xffffffffu, aL, i);
            float aVi = __shfl_sync(0xffffffffu, aV, i);
            float trij = tr[i*LL + j];
            av[i] = aLi + trij;
            mxL = fmaxf(mxL, av[i]);
            float vV = aVi + trij;
            if (vV > bestV){ bestV = vV; bidx = i; }
        }
        float ssum = 0.f;
        #pragma unroll
        for (int i=0;i<LL;i++) ssum += __expf(av[i]-mxL);
        float nwL = __logf(ssum) + mxL + lt;
        bool m = (t < len);
        if (lane<LL){
            if (m){ aL = nwL; aV = bestV + lt; }
            bp[t-1][lane] = m ? (unsigned char)bidx : (unsigned char)lane;
        }
    }
    float mx2 = -1e30f;
    #pragma unroll
    for (int i=0;i<LL;i++) mx2 = fmaxf(mx2, __shfl_sync(0xffffffffu, aL, i));
    float s2 = 0.f;
    #pragma unroll
    for (int i=0;i<LL;i++) s2 += __expf(__shfl_sync(0xffffffffu, aL, i) - mx2);
    float log_norm = __logf(s2) + mx2;
    int last = 0; float bv = -1e30f;
    #pragma unroll
    for (int i=0;i<LL;i++){
        float v = __shfl_sync(0xffffffffu, aV, i);
        if (v > bv){ bv = v; last = i; }
    }
    if (lane==0){
        outll[b] = un + bi - log_norm;
        int tag = last;
        outtags[b*TT + TT-1] = (float)tag;
        for (int t=TT-2;t>=0;t--){
            tag = bp[t][tag];
            outtags[b*TT + t] = (float)tag;
        }
    }
}

// ---------------- launch ----------------
extern "C" void kernel_launch(void* const* d_in, const int* in_sizes, int n_in,
                              void* d_out, int out_size)
{
    const int*   text  = (const int*)  d_in[0];
    const int*   sent  = (const int*)  d_in[1];
    const int*   labels= (const int*)  d_in[2];
    const float* wemb  = (const float*)d_in[3];
    const float* semb  = (const float*)d_in[4];
    const float* Wk_f  = (const float*)d_in[5];
    const float* Wr_f  = (const float*)d_in[6];
    const float* b_f   = (const float*)d_in[7];
    const float* Wk_b  = (const float*)d_in[8];
    const float* Wr_b  = (const float*)d_in[9];
    const float* b_b   = (const float*)d_in[10];
    const float* Wd    = (const float*)d_in[11];
    const float* bd    = (const float*)d_in[12];
    const float* trans = (const float*)d_in[13];
    float* out = (float*)d_out;

    cudaFuncSetAttribute(lstm_persistent, cudaFuncAttributeMaxDynamicSharedMemorySize, LSTM_SMEM);

    embed_kernel<<<(MM*150 + 255)/256, 256>>>(text, sent, wemb, semb);
    gemm_xz_kernel<<<dim3(128, 64), 256>>>(Wk_f, b_f, Wk_b, b_b);
    lstm_persistent<<<128, 256, LSTM_SMEM>>>(Wr_f, Wr_b);
    logits_kernel<<<256, 512>>>(Wd, bd, out);
    lens_kernel<<<BB, TT>>>(text, out + LEN_OFF);
    crf_kernel<<<BB, 32>>>(out, labels, trans, out + LLK_OFF, out + TAG_OFF);
}

// round 15
// speedup vs baseline: 1.0413x; 1.0388x over previous
#include <cuda_runtime.h>
#include <cuda_bf16.h>
#include <math.h>

typedef unsigned long long u64;
typedef unsigned u32;

#define BB 64
#define TT 256
#define DD 600
#define HH 512
#define GG 2048
#define LL 9
#define MM (BB*TT)

#define LEN_OFF (MM*LL)
#define LLK_OFF (LEN_OFF + BB)
#define TAG_OFF (LLK_OFF + BB)

// -------- scratch (device globals) --------
__device__ float g_x[(size_t)MM*DD];
__device__ float g_xz[2][(size_t)MM*GG];
__device__ __align__(16) uint2 g_hB[2][TT][BB][HH/2];  // [dir][t][b][u-pair] {bf16x2 hi, bf16x2 mid}
__device__ int g_lens[BB];
__device__ u32 g_flag[2][2][32][32];                   // [dir][bh][cg][pad] - 128B per flag

__device__ __forceinline__ float sigf(float x){ return 1.f/(1.f+__expf(-x)); }
__device__ __forceinline__ float tanhfast(float x){
    x = fminf(fmaxf(x, -15.f), 15.f);
    float e = __expf(2.f*x);
    return (e-1.f)/(e+1.f);
}
__device__ __forceinline__ unsigned f2tf(float f){
    unsigned r; asm("cvt.rna.tf32.f32 %0,%1;" : "=r"(r) : "f"(f)); return r;
}
__device__ __forceinline__ void mma8(float* d, const unsigned* a, const unsigned* b){
    asm("mma.sync.aligned.m16n8k8.row.col.f32.tf32.tf32.f32 "
        "{%0,%1,%2,%3},{%4,%5,%6,%7},{%8,%9},{%0,%1,%2,%3};"
        : "+f"(d[0]),"+f"(d[1]),"+f"(d[2]),"+f"(d[3])
        : "r"(a[0]),"r"(a[1]),"r"(a[2]),"r"(a[3]),"r"(b[0]),"r"(b[1]));
}
__device__ __forceinline__ void mma16(float* d, const unsigned* a, const unsigned* b){
    asm("mma.sync.aligned.m16n8k16.row.col.f32.bf16.bf16.f32 "
        "{%0,%1,%2,%3},{%4,%5,%6,%7},{%8,%9},{%0,%1,%2,%3};"
        : "+f"(d[0]),"+f"(d[1]),"+f"(d[2]),"+f"(d[3])
        : "r"(a[0]),"r"(a[1]),"r"(a[2]),"r"(a[3]),"r"(b[0]),"r"(b[1]));
}
__device__ __forceinline__ void bfsplit(float w, unsigned short& hi, unsigned short& mid){
    __nv_bfloat16 h = __float2bfloat16_rn(w);
    float r = w - __bfloat162float(h);
    __nv_bfloat16 m = __float2bfloat16_rn(r);
    hi = __bfloat16_as_ushort(h); mid = __bfloat16_as_ushort(m);
}
__device__ __forceinline__ float bflo(u32 v){ return __uint_as_float(v<<16); }
__device__ __forceinline__ float bfhi(u32 v){ return __uint_as_float(v & 0xffff0000u); }

// ---------------- embedding gather (float4) + flag reset ----------------
__global__ void embed_kernel(const int* __restrict__ text, const int* __restrict__ sent,
                             const float* __restrict__ wemb, const float* __restrict__ semb)
{
    int idx = blockIdx.x*blockDim.x + threadIdx.x;
    if (idx < 4096) ((u32*)g_flag)[idx] = 0;
    if (idx >= MM*150) return;
    int e4 = idx % 150, bt = idx / 150;
    float4 v;
    if (e4 < 75) v = ((const float4*)(wemb + (long)text[bt]*300))[e4];
    else         v = ((const float4*)(semb + (long)sent[bt]*300))[e4-75];
    ((float4*)g_x)[idx] = v;
}

// ---------------- xz = x @ Wk + b  (TF32 mma.sync, 128x128 tile, double-buffered) ----------------
// grid (128 m-tiles, 32 n-blocks [16/dir]); 512 thr = 16 warps (4x4 of 32x32).
#define AST 28
#define WST 132
#define GX_SMEM ((2*128*AST + 2*24*WST)*4)
__global__ void __launch_bounds__(512,1) gemm_xz_kernel(const float* __restrict__ Wk_f, const float* __restrict__ b_f,
                                                        const float* __restrict__ Wk_b, const float* __restrict__ b_b)
{
    extern __shared__ unsigned gsm[];
    unsigned* As = gsm;                    // [2][128*AST]
    unsigned* Ws = gsm + 2*128*AST;        // [2][24*WST]

    int tid = threadIdx.x;
    int warp = tid>>5, lane = tid&31;
    int g = lane>>2, tig = lane&3;
    int m0g = blockIdx.x*128;
    int nb  = blockIdx.y;
    const float* Bmat = (nb>=16)? Wk_b : Wk_f;
    const float* bias = (nb>=16)? b_b  : b_f;
    float* C = (nb>=16)? g_xz[1] : g_xz[0];
    int n0g = (nb&15)*128;
    int wm = (warp>>2)*32;
    int wn = (warp&3)*32;

    float acc[2][4][4];
    #pragma unroll
    for (int mt=0;mt<2;mt++)
        #pragma unroll
        for (int nt=0;nt<4;nt++)
            #pragma unroll
            for (int r=0;r<4;r++) acc[mt][nt][r]=0.f;

    float4 pa[2], pw[2];
    // prologue: chunk 0 loads (A: 768 float4 = 128 rows x 6; W: 768 float4 = 24 k x 32)
    #pragma unroll
    for (int q=0;q<2;q++){
        int i = tid + q*512;
        if (i < 768){
            int row = i/6, j = i%6;
            pa[q] = *(const float4*)&g_x[(long)(m0g+row)*DD + j*4];
            int k = i>>5, nq = i&31;
            pw[q] = *(const float4*)&Bmat[(long)k*GG + n0g + nq*4];
        }
    }
    #pragma unroll
    for (int q=0;q<2;q++){
        int i = tid + q*512;
        if (i < 768){
            int row = i/6, j = i%6;
            unsigned* d = &As[row*AST + j*4];
            d[0]=f2tf(pa[q].x); d[1]=f2tf(pa[q].y); d[2]=f2tf(pa[q].z); d[3]=f2tf(pa[q].w);
            int k = i>>5, nq = i&31;
            unsigned* dw = &Ws[k*WST + nq*4];
            dw[0]=f2tf(pw[q].x); dw[1]=f2tf(pw[q].y); dw[2]=f2tf(pw[q].z); dw[3]=f2tf(pw[q].w);
        }
    }
    __syncthreads();

    for (int ch=0; ch<25; ch++){
        int cur = ch&1;
        if (ch < 24){
            int kb = (ch+1)*24;
            #pragma unroll
            for (int q=0;q<2;q++){
                int i = tid + q*512;
                if (i < 768){
                    int row = i/6, j = i%6;
                    pa[q] = *(const float4*)&g_x[(long)(m0g+row)*DD + kb + j*4];
                    int k = i>>5, nq = i&31;
                    pw[q] = *(const float4*)&Bmat[(long)(kb+k)*GG + n0g + nq*4];
                }
            }
        }
        const unsigned* Ab = &As[cur*128*AST];
        const unsigned* Wb = &Ws[cur*24*WST];
        #pragma unroll
        for (int ks=0;ks<3;ks++){
            int kb = ks*8;
            unsigned a[2][4], b[4][2];
            #pragma unroll
            for (int mt=0;mt<2;mt++){
                int r0 = wm + mt*16;
                a[mt][0] = Ab[(r0+g  )*AST + kb+tig  ];
                a[mt][1] = Ab[(r0+g+8)*AST + kb+tig  ];
                a[mt][2] = Ab[(r0+g  )*AST + kb+tig+4];
                a[mt][3] = Ab[(r0+g+8)*AST + kb+tig+4];
            }
            #pragma unroll
            for (int nt=0;nt<4;nt++){
                int c0 = wn + nt*8 + g;
                b[nt][0] = Wb[(kb+tig  )*WST + c0];
                b[nt][1] = Wb[(kb+tig+4)*WST + c0];
            }
            #pragma unroll
            for (int mt=0;mt<2;mt++)
                #pragma unroll
                for (int nt=0;nt<4;nt++)
                    mma8(acc[mt][nt], a[mt], b[nt]);
        }
        if (ch < 24){
            int nxt = (ch+1)&1;
            unsigned* An = &As[nxt*128*AST];
            unsigned* Wn = &Ws[nxt*24*WST];
            #pragma unroll
            for (int q=0;q<2;q++){
                int i = tid + q*512;
                if (i < 768){
                    int row = i/6, j = i%6;
                    unsigned* d = &An[row*AST + j*4];
                    d[0]=f2tf(pa[q].x); d[1]=f2tf(pa[q].y); d[2]=f2tf(pa[q].z); d[3]=f2tf(pa[q].w);
                    int k = i>>5, nq = i&31;
                    unsigned* dw = &Wn[k*WST + nq*4];
                    dw[0]=f2tf(pw[q].x); dw[1]=f2tf(pw[q].y); dw[2]=f2tf(pw[q].z); dw[3]=f2tf(pw[q].w);
                }
            }
        }
        __syncthreads();
    }

    #pragma unroll
    for (int mt=0;mt<2;mt++){
        int row0 = m0g + wm + mt*16 + g;
        #pragma unroll
        for (int nt=0;nt<4;nt++){
            int col = n0g + wn + nt*8 + 2*tig;
            float b0 = bias[col], b1 = bias[col+1];
            float2 o0 = {acc[mt][nt][0]+b0, acc[mt][nt][1]+b1};
            float2 o1 = {acc[mt][nt][2]+b0, acc[mt][nt][3]+b1};
            *(float2*)&C[(long)row0*GG + col]     = o0;
            *(float2*)&C[(long)(row0+8)*GG + col] = o1;
        }
    }
}

// ---------------- persistent bidirectional LSTM (R13 known-good) ----------------
#define OFF_AH  32768
#define OFF_AM  41088
#define OFF_RB  49408
#define LSTM_SMEM ((49408 + 2*2176)*4)
__global__ void __launch_bounds__(256,1) lstm_persistent(const float* __restrict__ Wr_f,
                                                         const float* __restrict__ Wr_b)
{
    extern __shared__ u32 sm[];
    uint4* WFs = (uint4*)sm;
    u32*   AHs = sm + OFF_AH;     // [m(32)][kp(256)] stride 260
    u32*   AMs = sm + OFF_AM;
    float* Rbuf= (float*)(sm + OFF_RB);   // 2 x 2176 (step parity)

    int tid = threadIdx.x, bid = blockIdx.x;
    int dir = bid>>6, rr = bid&63, bh = rr>>5, cg = rr&31;
    int b0 = bh*32, u0 = cg*16;
    const float* Wr = dir ? Wr_b : Wr_f;
    const float* xz = g_xz[dir];

    // stage W fragments (once)
    for (int i = tid; i < 8192; i += 256){
        int ntile = i>>10, kt = (i>>5)&31, ln = i&31;
        int q = ntile>>1, uhx = ntile&1, gg = ln>>2, tg = ln&3;
        int col = q*HH + u0 + uhx*8 + gg;
        int p0 = kt*8+tg, p1 = p0+4;
        float w00 = Wr[(long)(2*p0  )*GG + col];
        float w01 = Wr[(long)(2*p0+1)*GG + col];
        float w10 = Wr[(long)(2*p1  )*GG + col];
        float w11 = Wr[(long)(2*p1+1)*GG + col];
        unsigned short h0,m0,h1,m1,h2,m2,h3,m3;
        bfsplit(w00,h0,m0); bfsplit(w01,h1,m1);
        bfsplit(w10,h2,m2); bfsplit(w11,h3,m3);
        uint4 o;
        o.x = ((u32)h1<<16)|h0; o.y = ((u32)h3<<16)|h2;
        o.z = ((u32)m1<<16)|m0; o.w = ((u32)m3<<16)|m2;
        WFs[i] = o;
    }

    int lane = tid&31, w = tid>>5;
    int g = lane>>2, tig = lane&3;
    int khalf = w>>2, wl = w&3;
    int mt = wl>>1, uh = wl&1;
    int wq = uh*1024 + lane;
    int r0 = (mt*16+g)*260, r1 = r0 + 8*260;
    int kt0 = khalf*16;
    int gtid = tid&127;
    int barid = 8 + khalf;
    float cst[4] = {0.f,0.f,0.f,0.f};
    __syncthreads();

    for (int s=0; s<TT; s++){
        int t = dir ? (TT-1-s) : s;

        // xz addends (warps 0-3 only)
        float2 pz[4][2];
        if (tid < 128){
            #pragma unroll
            for (int q=0;q<4;q++)
                #pragma unroll
                for (int bi=0;bi<2;bi++){
                    int brow = b0 + mt*16 + g + bi*8;
                    pz[q][bi] = *(const float2*)&xz[((long)brow*TT + t)*GG + q*HH + u0 + uh*8 + 2*tig];
                }
        }

        float acc[4][4];
        #pragma unroll
        for (int q=0;q<4;q++)
            #pragma unroll
            for (int r=0;r<4;r++) acc[q][r]=0.f;

        if (s){
            // wait for the 16 producers this half-group needs (parallel poll)
            if (wl == 0){
                if (lane < 16){
                    const u32* fp = &g_flag[dir][bh][khalf*16 + lane][0];
                    u32 v;
                    while (1){
                        asm volatile("ld.acquire.gpu.global.u32 %0,[%1];" : "=r"(v) : "l"(fp) : "memory");
                        if (v >= (u32)s) break;
                        __nanosleep(20);
                    }
                }
                __syncwarp();
            }
            asm volatile("bar.sync %0, 128;" :: "r"(barid) : "memory");

            int tp = dir ? (t+1) : (t-1);
            const uint4* src = (const uint4*)&g_hB[dir][tp][b0][0];   // 128 uint4 per row
            uint4 pf[8];
            #pragma unroll
            for (int j=0;j<8;j++){
                int idx = j*128 + gtid;
                int m = idx>>5, c = idx&31;
                pf[j] = __ldcg(&src[m*128 + khalf*64 + c]);
            }
            #pragma unroll
            for (int j=0;j<8;j++){
                int idx = j*128 + gtid;
                int m = idx>>5, c = idx&31;
                int up = khalf*128 + c*2;
                AHs[m*260 + up  ] = pf[j].x;  AMs[m*260 + up  ] = pf[j].y;
                AHs[m*260 + up+1] = pf[j].z;  AMs[m*260 + up+1] = pf[j].w;
            }
            asm volatile("bar.sync %0, 128;" :: "r"(barid) : "memory");
            // prefetch quarter 1
            #pragma unroll
            for (int j=0;j<8;j++){
                int idx = j*128 + gtid;
                int m = idx>>5, c = idx&31;
                pf[j] = __ldcg(&src[m*128 + khalf*64 + 32 + c]);
            }
            // mma on quarter 0
            #pragma unroll 4
            for (int kk=0; kk<8; kk++){
                int kt = kt0 + kk;
                int kp0 = kt*8+tig, kp1 = kp0+4;
                u32 ah[4], am[4];
                ah[0]=AHs[r0+kp0]; ah[1]=AHs[r1+kp0];
                ah[2]=AHs[r0+kp1]; ah[3]=AHs[r1+kp1];
                am[0]=AMs[r0+kp0]; am[1]=AMs[r1+kp0];
                am[2]=AMs[r0+kp1]; am[3]=AMs[r1+kp1];
                #pragma unroll
                for (int q=0;q<4;q++){
                    uint4 wv = WFs[q*2048 + kt*32 + wq];
                    u32 bh_[2] = {wv.x, wv.y};
                    u32 bm_[2] = {wv.z, wv.w};
                    mma16(acc[q], ah, bh_);
                    mma16(acc[q], ah, bm_);
                    mma16(acc[q], am, bh_);
                }
            }
            // store quarter 1
            #pragma unroll
            for (int j=0;j<8;j++){
                int idx = j*128 + gtid;
                int m = idx>>5, c = idx&31;
                int up = khalf*128 + 64 + c*2;
                AHs[m*260 + up  ] = pf[j].x;  AMs[m*260 + up  ] = pf[j].y;
                AHs[m*260 + up+1] = pf[j].z;  AMs[m*260 + up+1] = pf[j].w;
            }
            asm volatile("bar.sync %0, 128;" :: "r"(barid) : "memory");
            // mma on quarter 1
            #pragma unroll 4
            for (int kk=8; kk<16; kk++){
                int kt = kt0 + kk;
                int kp0 = kt*8+tig, kp1 = kp0+4;
                u32 ah[4], am[4];
                ah[0]=AHs[r0+kp0]; ah[1]=AHs[r1+kp0];
                ah[2]=AHs[r0+kp1]; ah[3]=AHs[r1+kp1];
                am[0]=AMs[r0+kp0]; am[1]=AMs[r1+kp0];
                am[2]=AMs[r0+kp1]; am[3]=AMs[r1+kp1];
                #pragma unroll
                for (int q=0;q<4;q++){
                    uint4 wv = WFs[q*2048 + kt*32 + wq];
                    u32 bh_[2] = {wv.x, wv.y};
                    u32 bm_[2] = {wv.z, wv.w};
                    mma16(acc[q], ah, bh_);
                    mma16(acc[q], ah, bm_);
                    mma16(acc[q], am, bh_);
                }
            }

            // split-K reduce (parity-buffered): warps 4-7 -> SMEM -> warps 0-3
            float* RB = Rbuf + (s&1)*2176;
            if (tid >= 128){
                float* rb = &RB[(tid-128)*17];
                #pragma unroll
                for (int q=0;q<4;q++)
                    #pragma unroll
                    for (int r=0;r<4;r++) rb[q*4+r] = acc[q][r];
            }
            __syncthreads();
            if (tid < 128){
                const float* rb = &RB[tid*17];
                #pragma unroll
                for (int q=0;q<4;q++)
                    #pragma unroll
                    for (int r=0;r<4;r++) acc[q][r] += rb[q*4+r];
            }
        }

        // gates + state update + publish (warps 0-3)
        if (tid < 128){
            #pragma unroll
            for (int bi=0;bi<2;bi++){
                int brow = b0 + mt*16 + g + bi*8;
                float zi0 = acc[0][bi*2  ] + pz[0][bi].x;
                float zi1 = acc[0][bi*2+1] + pz[0][bi].y;
                float zf0 = acc[1][bi*2  ] + pz[1][bi].x;
                float zf1 = acc[1][bi*2+1] + pz[1][bi].y;
                float zg0 = acc[2][bi*2  ] + pz[2][bi].x;
                float zg1 = acc[2][bi*2+1] + pz[2][bi].y;
                float zo0 = acc[3][bi*2  ] + pz[3][bi].x;
                float zo1 = acc[3][bi*2+1] + pz[3][bi].y;
                float cn0 = sigf(zf0)*cst[bi*2  ] + sigf(zi0)*tanhfast(zg0);
                float cn1 = sigf(zf1)*cst[bi*2+1] + sigf(zi1)*tanhfast(zg1);
                cst[bi*2  ] = cn0; cst[bi*2+1] = cn1;
                float h0 = sigf(zo0)*tanhfast(cn0);
                float h1 = sigf(zo1)*tanhfast(cn1);
                unsigned short hh0,hm0,hh1,hm1;
                bfsplit(h0,hh0,hm0); bfsplit(h1,hh1,hm1);
                int up = cg*8 + uh*4 + tig;
                uint2 pk;
                pk.x = ((u32)hh1<<16) | hh0;
                pk.y = ((u32)hm1<<16) | hm0;
                g_hB[dir][t][brow][up] = pk;
            }
            __threadfence();
            asm volatile("bar.sync 8, 128;" ::: "memory");
            if (tid == 0){
                asm volatile("st.release.gpu.global.u32 [%0],%1;"
                             :: "l"(&g_flag[dir][bh][cg][0]), "r"((u32)(s+1)) : "memory");
            }
        }
    }
}

// ---------------- logits = [hf|hb] @ Wd + bd ----------------
__global__ void __launch_bounds__(512) logits_kernel(const float* __restrict__ Wd, const float* __restrict__ bd,
                                                     float* __restrict__ out)
{
    __shared__ float sW[1024*LL];
    int t = blockIdx.x, tid = threadIdx.x;
    for (int i=tid; i<1024*LL; i+=512) sW[i] = Wd[i];
    __syncthreads();

    int warp = tid>>5, lane = tid&31;
    int b0 = warp*4;
    float acc[4][LL];
    #pragma unroll
    for (int r=0;r<4;r++)
        #pragma unroll
        for (int l=0;l<LL;l++) acc[r][l]=0.f;

    #pragma unroll
    for (int it=0; it<8; it++){
        int dirsel = it>>2;
        int uc = (it&3)*128 + lane*4;
        int c4 = (it&3)*32 + lane;
        float4 v[4];
        #pragma unroll
        for (int r=0;r<4;r++){
            uint4 p = *(const uint4*)((const u32*)&g_hB[dirsel][t][b0+r][0] + c4*4);
            v[r].x = bflo(p.x) + bflo(p.y);
            v[r].y = bfhi(p.x) + bfhi(p.y);
            v[r].z = bflo(p.z) + bflo(p.w);
            v[r].w = bfhi(p.z) + bfhi(p.w);
        }
        int wbase = (dirsel*HH + uc)*LL;
        #pragma unroll
        for (int e=0;e<4;e++){
            float w9[LL];
            #pragma unroll
            for (int l=0;l<LL;l++) w9[l] = sW[wbase + e*LL + l];
            #pragma unroll
            for (int r=0;r<4;r++){
                float hv = (e==0)?v[r].x:(e==1)?v[r].y:(e==2)?v[r].z:v[r].w;
                #pragma unroll
                for (int l=0;l<LL;l++) acc[r][l] += hv*w9[l];
            }
        }
    }
    #pragma unroll
    for (int r=0;r<4;r++)
        #pragma unroll
        for (int l=0;l<LL;l++){
            float v = acc[r][l];
            #pragma unroll
            for (int off=16;off;off>>=1) v += __shfl_down_sync(0xffffffffu, v, off);
            acc[r][l] = v;
        }
    if (lane==0){
        #pragma unroll
        for (int r=0;r<4;r++)
            #pragma unroll
            for (int l=0;l<LL;l++)
                out[((long)(b0+r)*TT + t)*LL + l] = acc[r][l] + bd[l];
    }
}

// ---------------- text lens ----------------
__global__ void lens_kernel(const int* __restrict__ text, float* __restrict__ outlen)
{
    __shared__ int sred[TT];
    int b = blockIdx.x, tid = threadIdx.x;
    sred[tid] = (text[b*TT+tid] != 0) ? 1 : 0;
    __syncthreads();
    for (int s=TT/2; s; s>>=1){
        if (tid < s) sred[tid] += sred[tid+s];
        __syncthreads();
    }
    if (tid==0){ g_lens[b] = sred[0]; outlen[b] = (float)sred[0]; }
}

// ---------------- fused CRF log-likelihood + Viterbi ----------------
__global__ void crf_kernel(const float* __restrict__ logits, const int* __restrict__ labels,
                           const float* __restrict__ trans, float* __restrict__ outll,
                           float* __restrict__ outtags)
{
    int b = blockIdx.x, lane = threadIdx.x;
    __shared__ float tr[LL*LL];
    __shared__ unsigned char bp[TT-1][LL];
    for (int i=lane;i<LL*LL;i+=32) tr[i]=trans[i];
    __syncwarp();
    int len = g_lens[b];
    const float* lg = logits + (long)b*TT*LL;
    const int* lab = labels + b*TT;

    float un=0.f, bi=0.f;
    for (int t=lane;t<TT;t+=32){
        if (t < len)           un += lg[t*LL + lab[t]];
        if (t >= 1 && t < len) bi += tr[lab[t-1]*LL + lab[t]];
    }
    #pragma unroll
    for (int off=16;off;off>>=1){
        un += __shfl_down_sync(0xffffffffu, un, off);
        bi += __shfl_down_sync(0xffffffffu, bi, off);
    }

    int j = (lane<LL)? lane : 0;
    float aL = (lane<LL)? lg[lane] : -1e30f;
    float aV = aL;
    for (int t=1;t<TT;t++){
        float lt = (lane<LL)? lg[t*LL+lane] : 0.f;
        float av[LL]; float mxL = -1e30f;
        float bestV = -1e30f; int bidx = 0;
        #pragma unroll
        for (int i=0;i<LL;i++){
            float aLi = __shfl_sync(0xffffffffu, aL, i);
            float aVi = __shfl_sync(0xffffffffu, aV, i);
            float trij = tr[i*LL + j];
            av[i] = aLi + trij;
            mxL = fmaxf(mxL, av[i]);
            float vV = aVi + trij;
            if (vV > bestV){ bestV = vV; bidx = i; }
        }
        float ssum = 0.f;
        #pragma unroll
        for (int i=0;i<LL;i++) ssum += __expf(av[i]-mxL);
        float nwL = __logf(ssum) + mxL + lt;
        bool m = (t < len);
        if (lane<LL){
            if (m){ aL = nwL; aV = bestV + lt; }
            bp[t-1][lane] = m ? (unsigned char)bidx : (unsigned char)lane;
        }
    }
    float mx2 = -1e30f;
    #pragma unroll
    for (int i=0;i<LL;i++) mx2 = fmaxf(mx2, __shfl_sync(0xffffffffu, aL, i));
    float s2 = 0.f;
    #pragma unroll
    for (int i=0;i<LL;i++) s2 += __expf(__shfl_sync(0xffffffffu, aL, i) - mx2);
    float log_norm = __logf(s2) + mx2;
    int last = 0; float bv = -1e30f;
    #pragma unroll
    for (int i=0;i<LL;i++){
        float v = __shfl_sync(0xffffffffu, aV, i);
        if (v > bv){ bv = v; last = i; }
    }
    if (lane==0){
        outll[b] = un + bi - log_norm;
        int tag = last;
        outtags[b*TT + TT-1] = (float)tag;
        for (int t=TT-2;t>=0;t--){
            tag = bp[t][tag];
            outtags[b*TT + t] = (float)tag;
        }
    }
}

// ---------------- launch ----------------
extern "C" void kernel_launch(void* const* d_in, const int* in_sizes, int n_in,
                              void* d_out, int out_size)
{
    const int*   text  = (const int*)  d_in[0];
    const int*   sent  = (const int*)  d_in[1];
    const int*   labels= (const int*)  d_in[2];
    const float* wemb  = (const float*)d_in[3];
    const float* semb  = (const float*)d_in[4];
    const float* Wk_f  = (const float*)d_in[5];
    const float* Wr_f  = (const float*)d_in[6];
    const float* b_f   = (const float*)d_in[7];
    const float* Wk_b  = (const float*)d_in[8];
    const float* Wr_b  = (const float*)d_in[9];
    const float* b_b   = (const float*)d_in[10];
    const float* Wd    = (const float*)d_in[11];
    const float* bd    = (const float*)d_in[12];
    const float* trans = (const float*)d_in[13];
    float* out = (float*)d_out;

    cudaFuncSetAttribute(lstm_persistent, cudaFuncAttributeMaxDynamicSharedMemorySize, LSTM_SMEM);
    cudaFuncSetAttribute(gemm_xz_kernel, cudaFuncAttributeMaxDynamicSharedMemorySize, GX_SMEM);

    // lens first so lstm_persistent is the 4th launch (ncu -s 5 captures it)
    lens_kernel<<<BB, TT>>>(text, out + LEN_OFF);
    embed_kernel<<<(MM*150 + 255)/256, 256>>>(text, sent, wemb, semb);
    gemm_xz_kernel<<<dim3(128, 32), 512, GX_SMEM>>>(Wk_f, b_f, Wk_b, b_b);
    lstm_persistent<<<128, 256, LSTM_SMEM>>>(Wr_f, Wr_b);
    logits_kernel<<<256, 512>>>(Wd, bd, out);
    crf_kernel<<<BB, 32>>>(out, labels, trans, out + LLK_OFF, out + TAG_OFF);
}

// round 16
// speedup vs baseline: 1.0743x; 1.0317x over previous
#include <cuda_runtime.h>
#include <cuda_bf16.h>
#include <math.h>

typedef unsigned long long u64;
typedef unsigned u32;

#define BB 64
#define TT 256
#define DD 600
#define HH 512
#define GG 2048
#define LL 9
#define MM (BB*TT)

#define LEN_OFF (MM*LL)
#define LLK_OFF (LEN_OFF + BB)
#define TAG_OFF (LLK_OFF + BB)

// -------- scratch (device globals) --------
__device__ float g_x[(size_t)MM*DD];
__device__ float g_xz[2][(size_t)MM*GG];
__device__ __align__(16) uint2 g_hB[2][TT][BB][HH/2];  // [dir][t][b][u-pair] {bf16x2 hi, bf16x2 mid}
__device__ int g_lens[BB];
__device__ u32 g_flag[2][2][32][32];                   // [dir][bh][cg][pad] - 128B per flag

__device__ __forceinline__ float sigf(float x){ return 1.f/(1.f+__expf(-x)); }
__device__ __forceinline__ float tanhfast(float x){
    x = fminf(fmaxf(x, -15.f), 15.f);
    float e = __expf(2.f*x);
    return (e-1.f)/(e+1.f);
}
__device__ __forceinline__ unsigned f2tf(float f){
    unsigned r; asm("cvt.rna.tf32.f32 %0,%1;" : "=r"(r) : "f"(f)); return r;
}
__device__ __forceinline__ void mma8(float* d, const unsigned* a, const unsigned* b){
    asm("mma.sync.aligned.m16n8k8.row.col.f32.tf32.tf32.f32 "
        "{%0,%1,%2,%3},{%4,%5,%6,%7},{%8,%9},{%0,%1,%2,%3};"
        : "+f"(d[0]),"+f"(d[1]),"+f"(d[2]),"+f"(d[3])
        : "r"(a[0]),"r"(a[1]),"r"(a[2]),"r"(a[3]),"r"(b[0]),"r"(b[1]));
}
__device__ __forceinline__ void mma16(float* d, const unsigned* a, const unsigned* b){
    asm("mma.sync.aligned.m16n8k16.row.col.f32.bf16.bf16.f32 "
        "{%0,%1,%2,%3},{%4,%5,%6,%7},{%8,%9},{%0,%1,%2,%3};"
        : "+f"(d[0]),"+f"(d[1]),"+f"(d[2]),"+f"(d[3])
        : "r"(a[0]),"r"(a[1]),"r"(a[2]),"r"(a[3]),"r"(b[0]),"r"(b[1]));
}
__device__ __forceinline__ void bfsplit(float w, unsigned short& hi, unsigned short& mid){
    __nv_bfloat16 h = __float2bfloat16_rn(w);
    float r = w - __bfloat162float(h);
    __nv_bfloat16 m = __float2bfloat16_rn(r);
    hi = __bfloat16_as_ushort(h); mid = __bfloat16_as_ushort(m);
}
__device__ __forceinline__ float bflo(u32 v){ return __uint_as_float(v<<16); }
__device__ __forceinline__ float bfhi(u32 v){ return __uint_as_float(v & 0xffff0000u); }

// ---------------- embedding gather (float4) + flag reset ----------------
__global__ void embed_kernel(const int* __restrict__ text, const int* __restrict__ sent,
                             const float* __restrict__ wemb, const float* __restrict__ semb)
{
    int idx = blockIdx.x*blockDim.x + threadIdx.x;
    if (idx < 4096) ((u32*)g_flag)[idx] = 0;
    if (idx >= MM*150) return;
    int e4 = idx % 150, bt = idx / 150;
    float4 v;
    if (e4 < 75) v = ((const float4*)(wemb + (long)text[bt]*300))[e4];
    else         v = ((const float4*)(semb + (long)sent[bt]*300))[e4-75];
    ((float4*)g_x)[idx] = v;
}

// ---------------- xz = x @ Wk + b  (TF32 mma.sync, 128x128 tile, double-buffered) ----------------
#define AST 28
#define WST 132
#define GX_SMEM ((2*128*AST + 2*24*WST)*4)
__global__ void __launch_bounds__(512,1) gemm_xz_kernel(const float* __restrict__ Wk_f, const float* __restrict__ b_f,
                                                        const float* __restrict__ Wk_b, const float* __restrict__ b_b)
{
    extern __shared__ unsigned gsm[];
    unsigned* As = gsm;                    // [2][128*AST]
    unsigned* Ws = gsm + 2*128*AST;        // [2][24*WST]

    int tid = threadIdx.x;
    int warp = tid>>5, lane = tid&31;
    int g = lane>>2, tig = lane&3;
    int m0g = blockIdx.x*128;
    int nb  = blockIdx.y;
    const float* Bmat = (nb>=16)? Wk_b : Wk_f;
    const float* bias = (nb>=16)? b_b  : b_f;
    float* C = (nb>=16)? g_xz[1] : g_xz[0];
    int n0g = (nb&15)*128;
    int wm = (warp>>2)*32;
    int wn = (warp&3)*32;

    float acc[2][4][4];
    #pragma unroll
    for (int mt=0;mt<2;mt++)
        #pragma unroll
        for (int nt=0;nt<4;nt++)
            #pragma unroll
            for (int r=0;r<4;r++) acc[mt][nt][r]=0.f;

    float4 pa[2], pw[2];
    #pragma unroll
    for (int q=0;q<2;q++){
        int i = tid + q*512;
        if (i < 768){
            int row = i/6, j = i%6;
            pa[q] = *(const float4*)&g_x[(long)(m0g+row)*DD + j*4];
            int k = i>>5, nq = i&31;
            pw[q] = *(const float4*)&Bmat[(long)k*GG + n0g + nq*4];
        }
    }
    #pragma unroll
    for (int q=0;q<2;q++){
        int i = tid + q*512;
        if (i < 768){
            int row = i/6, j = i%6;
            unsigned* d = &As[row*AST + j*4];
            d[0]=f2tf(pa[q].x); d[1]=f2tf(pa[q].y); d[2]=f2tf(pa[q].z); d[3]=f2tf(pa[q].w);
            int k = i>>5, nq = i&31;
            unsigned* dw = &Ws[k*WST + nq*4];
            dw[0]=f2tf(pw[q].x); dw[1]=f2tf(pw[q].y); dw[2]=f2tf(pw[q].z); dw[3]=f2tf(pw[q].w);
        }
    }
    __syncthreads();

    for (int ch=0; ch<25; ch++){
        int cur = ch&1;
        if (ch < 24){
            int kb = (ch+1)*24;
            #pragma unroll
            for (int q=0;q<2;q++){
                int i = tid + q*512;
                if (i < 768){
                    int row = i/6, j = i%6;
                    pa[q] = *(const float4*)&g_x[(long)(m0g+row)*DD + kb + j*4];
                    int k = i>>5, nq = i&31;
                    pw[q] = *(const float4*)&Bmat[(long)(kb+k)*GG + n0g + nq*4];
                }
            }
        }
        const unsigned* Ab = &As[cur*128*AST];
        const unsigned* Wb = &Ws[cur*24*WST];
        #pragma unroll
        for (int ks=0;ks<3;ks++){
            int kb = ks*8;
            unsigned a[2][4], b[4][2];
            #pragma unroll
            for (int mt=0;mt<2;mt++){
                int r0 = wm + mt*16;
                a[mt][0] = Ab[(r0+g  )*AST + kb+tig  ];
                a[mt][1] = Ab[(r0+g+8)*AST + kb+tig  ];
                a[mt][2] = Ab[(r0+g  )*AST + kb+tig+4];
                a[mt][3] = Ab[(r0+g+8)*AST + kb+tig+4];
            }
            #pragma unroll
            for (int nt=0;nt<4;nt++){
                int c0 = wn + nt*8 + g;
                b[nt][0] = Wb[(kb+tig  )*WST + c0];
                b[nt][1] = Wb[(kb+tig+4)*WST + c0];
            }
            #pragma unroll
            for (int mt=0;mt<2;mt++)
                #pragma unroll
                for (int nt=0;nt<4;nt++)
                    mma8(acc[mt][nt], a[mt], b[nt]);
        }
        if (ch < 24){
            int nxt = (ch+1)&1;
            unsigned* An = &As[nxt*128*AST];
            unsigned* Wn = &Ws[nxt*24*WST];
            #pragma unroll
            for (int q=0;q<2;q++){
                int i = tid + q*512;
                if (i < 768){
                    int row = i/6, j = i%6;
                    unsigned* d = &An[row*AST + j*4];
                    d[0]=f2tf(pa[q].x); d[1]=f2tf(pa[q].y); d[2]=f2tf(pa[q].z); d[3]=f2tf(pa[q].w);
                    int k = i>>5, nq = i&31;
                    unsigned* dw = &Wn[k*WST + nq*4];
                    dw[0]=f2tf(pw[q].x); dw[1]=f2tf(pw[q].y); dw[2]=f2tf(pw[q].z); dw[3]=f2tf(pw[q].w);
                }
            }
        }
        __syncthreads();
    }

    #pragma unroll
    for (int mt=0;mt<2;mt++){
        int row0 = m0g + wm + mt*16 + g;
        #pragma unroll
        for (int nt=0;nt<4;nt++){
            int col = n0g + wn + nt*8 + 2*tig;
            float b0 = bias[col], b1 = bias[col+1];
            float2 o0 = {acc[mt][nt][0]+b0, acc[mt][nt][1]+b1};
            float2 o1 = {acc[mt][nt][2]+b0, acc[mt][nt][3]+b1};
            *(float2*)&C[(long)row0*GG + col]     = o0;
            *(float2*)&C[(long)(row0+8)*GG + col] = o1;
        }
    }
}

// ---------------- persistent bidirectional LSTM ----------------
// 128 blocks x 256 thr (8 warps, split-K). Per-warp flag polling (no post-poll bar),
// release-only publish (no threadfence), hot spin.
#define OFF_AH  32768
#define OFF_AM  41088
#define OFF_RB  49408
#define LSTM_SMEM ((49408 + 2*2176)*4)
__global__ void __launch_bounds__(256,1) lstm_persistent(const float* __restrict__ Wr_f,
                                                         const float* __restrict__ Wr_b)
{
    extern __shared__ u32 sm[];
    uint4* WFs = (uint4*)sm;
    u32*   AHs = sm + OFF_AH;     // [m(32)][kp(256)] stride 260
    u32*   AMs = sm + OFF_AM;
    float* Rbuf= (float*)(sm + OFF_RB);   // 2 x 2176 (step parity)

    int tid = threadIdx.x, bid = blockIdx.x;
    int dir = bid>>6, rr = bid&63, bh = rr>>5, cg = rr&31;
    int b0 = bh*32, u0 = cg*16;
    const float* Wr = dir ? Wr_b : Wr_f;
    const float* xz = g_xz[dir];

    // stage W fragments (once)
    for (int i = tid; i < 8192; i += 256){
        int ntile = i>>10, kt = (i>>5)&31, ln = i&31;
        int q = ntile>>1, uhx = ntile&1, gg = ln>>2, tg = ln&3;
        int col = q*HH + u0 + uhx*8 + gg;
        int p0 = kt*8+tg, p1 = p0+4;
        float w00 = Wr[(long)(2*p0  )*GG + col];
        float w01 = Wr[(long)(2*p0+1)*GG + col];
        float w10 = Wr[(long)(2*p1  )*GG + col];
        float w11 = Wr[(long)(2*p1+1)*GG + col];
        unsigned short h0,m0,h1,m1,h2,m2,h3,m3;
        bfsplit(w00,h0,m0); bfsplit(w01,h1,m1);
        bfsplit(w10,h2,m2); bfsplit(w11,h3,m3);
        uint4 o;
        o.x = ((u32)h1<<16)|h0; o.y = ((u32)h3<<16)|h2;
        o.z = ((u32)m1<<16)|m0; o.w = ((u32)m3<<16)|m2;
        WFs[i] = o;
    }

    int lane = tid&31, w = tid>>5;
    int g = lane>>2, tig = lane&3;
    int khalf = w>>2, wl = w&3;
    int mt = wl>>1, uh = wl&1;
    int wq = uh*1024 + lane;
    int r0 = (mt*16+g)*260, r1 = r0 + 8*260;
    int kt0 = khalf*16;
    int gtid = tid&127;
    int barid = 8 + khalf;
    float cst[4] = {0.f,0.f,0.f,0.f};
    __syncthreads();

    for (int s=0; s<TT; s++){
        int t = dir ? (TT-1-s) : s;

        // xz addends (warps 0-3 only)
        float2 pz[4][2];
        if (tid < 128){
            #pragma unroll
            for (int q=0;q<4;q++)
                #pragma unroll
                for (int bi=0;bi<2;bi++){
                    int brow = b0 + mt*16 + g + bi*8;
                    pz[q][bi] = *(const float2*)&xz[((long)brow*TT + t)*GG + q*HH + u0 + uh*8 + 2*tig];
                }
        }

        float acc[4][4];
        #pragma unroll
        for (int q=0;q<4;q++)
            #pragma unroll
            for (int r=0;r<4;r++) acc[q][r]=0.f;

        if (s){
            // every warp polls its half-group's 16 producer flags (hot spin, no bar)
            if (lane < 16){
                const u32* fp = &g_flag[dir][bh][khalf*16 + lane][0];
                u32 v;
                while (1){
                    asm volatile("ld.acquire.gpu.global.u32 %0,[%1];" : "=r"(v) : "l"(fp) : "memory");
                    if (v >= (u32)s) break;
                }
            }
            __syncwarp();

            int tp = dir ? (t+1) : (t-1);
            const uint4* src = (const uint4*)&g_hB[dir][tp][b0][0];   // 128 uint4 per row
            uint4 pf[8];
            #pragma unroll
            for (int j=0;j<8;j++){
                int idx = j*128 + gtid;
                int m = idx>>5, c = idx&31;
                pf[j] = __ldcg(&src[m*128 + khalf*64 + c]);
            }
            #pragma unroll
            for (int j=0;j<8;j++){
                int idx = j*128 + gtid;
                int m = idx>>5, c = idx&31;
                int up = khalf*128 + c*2;
                AHs[m*260 + up  ] = pf[j].x;  AMs[m*260 + up  ] = pf[j].y;
                AHs[m*260 + up+1] = pf[j].z;  AMs[m*260 + up+1] = pf[j].w;
            }
            asm volatile("bar.sync %0, 128;" :: "r"(barid) : "memory");
            // prefetch quarter 1
            #pragma unroll
            for (int j=0;j<8;j++){
                int idx = j*128 + gtid;
                int m = idx>>5, c = idx&31;
                pf[j] = __ldcg(&src[m*128 + khalf*64 + 32 + c]);
            }
            // mma on quarter 0
            #pragma unroll 4
            for (int kk=0; kk<8; kk++){
                int kt = kt0 + kk;
                int kp0 = kt*8+tig, kp1 = kp0+4;
                u32 ah[4], am[4];
                ah[0]=AHs[r0+kp0]; ah[1]=AHs[r1+kp0];
                ah[2]=AHs[r0+kp1]; ah[3]=AHs[r1+kp1];
                am[0]=AMs[r0+kp0]; am[1]=AMs[r1+kp0];
                am[2]=AMs[r0+kp1]; am[3]=AMs[r1+kp1];
                #pragma unroll
                for (int q=0;q<4;q++){
                    uint4 wv = WFs[q*2048 + kt*32 + wq];
                    u32 bh_[2] = {wv.x, wv.y};
                    u32 bm_[2] = {wv.z, wv.w};
                    mma16(acc[q], ah, bh_);
                    mma16(acc[q], ah, bm_);
                    mma16(acc[q], am, bh_);
                }
            }
            // store quarter 1
            #pragma unroll
            for (int j=0;j<8;j++){
                int idx = j*128 + gtid;
                int m = idx>>5, c = idx&31;
                int up = khalf*128 + 64 + c*2;
                AHs[m*260 + up  ] = pf[j].x;  AMs[m*260 + up  ] = pf[j].y;
                AHs[m*260 + up+1] = pf[j].z;  AMs[m*260 + up+1] = pf[j].w;
            }
            asm volatile("bar.sync %0, 128;" :: "r"(barid) : "memory");
            // mma on quarter 1
            #pragma unroll 4
            for (int kk=8; kk<16; kk++){
                int kt = kt0 + kk;
                int kp0 = kt*8+tig, kp1 = kp0+4;
                u32 ah[4], am[4];
                ah[0]=AHs[r0+kp0]; ah[1]=AHs[r1+kp0];
                ah[2]=AHs[r0+kp1]; ah[3]=AHs[r1+kp1];
                am[0]=AMs[r0+kp0]; am[1]=AMs[r1+kp0];
                am[2]=AMs[r0+kp1]; am[3]=AMs[r1+kp1];
                #pragma unroll
                for (int q=0;q<4;q++){
                    uint4 wv = WFs[q*2048 + kt*32 + wq];
                    u32 bh_[2] = {wv.x, wv.y};
                    u32 bm_[2] = {wv.z, wv.w};
                    mma16(acc[q], ah, bh_);
                    mma16(acc[q], ah, bm_);
                    mma16(acc[q], am, bh_);
                }
            }

            // split-K reduce (parity-buffered): warps 4-7 -> SMEM -> warps 0-3
            float* RB = Rbuf + (s&1)*2176;
            if (tid >= 128){
                float* rb = &RB[(tid-128)*17];
                #pragma unroll
                for (int q=0;q<4;q++)
                    #pragma unroll
                    for (int r=0;r<4;r++) rb[q*4+r] = acc[q][r];
            }
            __syncthreads();
            if (tid < 128){
                const float* rb = &RB[tid*17];
                #pragma unroll
                for (int q=0;q<4;q++)
                    #pragma unroll
                    for (int r=0;r<4;r++) acc[q][r] += rb[q*4+r];
            }
        }

        // gates + state update + publish (warps 0-3)
        if (tid < 128){
            #pragma unroll
            for (int bi=0;bi<2;bi++){
                int brow = b0 + mt*16 + g + bi*8;
                float zi0 = acc[0][bi*2  ] + pz[0][bi].x;
                float zi1 = acc[0][bi*2+1] + pz[0][bi].y;
                float zf0 = acc[1][bi*2  ] + pz[1][bi].x;
                float zf1 = acc[1][bi*2+1] + pz[1][bi].y;
                float zg0 = acc[2][bi*2  ] + pz[2][bi].x;
                float zg1 = acc[2][bi*2+1] + pz[2][bi].y;
                float zo0 = acc[3][bi*2  ] + pz[3][bi].x;
                float zo1 = acc[3][bi*2+1] + pz[3][bi].y;
                float cn0 = sigf(zf0)*cst[bi*2  ] + sigf(zi0)*tanhfast(zg0);
                float cn1 = sigf(zf1)*cst[bi*2+1] + sigf(zi1)*tanhfast(zg1);
                cst[bi*2  ] = cn0; cst[bi*2+1] = cn1;
                float h0 = sigf(zo0)*tanhfast(cn0);
                float h1 = sigf(zo1)*tanhfast(cn1);
                unsigned short hh0,hm0,hh1,hm1;
                bfsplit(h0,hh0,hm0); bfsplit(h1,hh1,hm1);
                int up = cg*8 + uh*4 + tig;
                uint2 pk;
                pk.x = ((u32)hh1<<16) | hh0;
                pk.y = ((u32)hm1<<16) | hm0;
                g_hB[dir][t][brow][up] = pk;
            }
            asm volatile("bar.sync 8, 128;" ::: "memory");
            if (tid == 0){
                asm volatile("st.release.gpu.global.u32 [%0],%1;"
                             :: "l"(&g_flag[dir][bh][cg][0]), "r"((u32)(s+1)) : "memory");
            }
        }
    }
}

// ---------------- logits = [hf|hb] @ Wd + bd ----------------
__global__ void __launch_bounds__(512) logits_kernel(const float* __restrict__ Wd, const float* __restrict__ bd,
                                                     float* __restrict__ out)
{
    __shared__ float sW[1024*LL];
    int t = blockIdx.x, tid = threadIdx.x;
    for (int i=tid; i<1024*LL; i+=512) sW[i] = Wd[i];
    __syncthreads();

    int warp = tid>>5, lane = tid&31;
    int b0 = warp*4;
    float acc[4][LL];
    #pragma unroll
    for (int r=0;r<4;r++)
        #pragma unroll
        for (int l=0;l<LL;l++) acc[r][l]=0.f;

    #pragma unroll
    for (int it=0; it<8; it++){
        int dirsel = it>>2;
        int uc = (it&3)*128 + lane*4;
        int c4 = (it&3)*32 + lane;
        float4 v[4];
        #pragma unroll
        for (int r=0;r<4;r++){
            uint4 p = *(const uint4*)((const u32*)&g_hB[dirsel][t][b0+r][0] + c4*4);
            v[r].x = bflo(p.x) + bflo(p.y);
            v[r].y = bfhi(p.x) + bfhi(p.y);
            v[r].z = bflo(p.z) + bflo(p.w);
            v[r].w = bfhi(p.z) + bfhi(p.w);
        }
        int wbase = (dirsel*HH + uc)*LL;
        #pragma unroll
        for (int e=0;e<4;e++){
            float w9[LL];
            #pragma unroll
            for (int l=0;l<LL;l++) w9[l] = sW[wbase + e*LL + l];
            #pragma unroll
            for (int r=0;r<4;r++){
                float hv = (e==0)?v[r].x:(e==1)?v[r].y:(e==2)?v[r].z:v[r].w;
                #pragma unroll
                for (int l=0;l<LL;l++) acc[r][l] += hv*w9[l];
            }
        }
    }
    #pragma unroll
    for (int r=0;r<4;r++)
        #pragma unroll
        for (int l=0;l<LL;l++){
            float v = acc[r][l];
            #pragma unroll
            for (int off=16;off;off>>=1) v += __shfl_down_sync(0xffffffffu, v, off);
            acc[r][l] = v;
        }
    if (lane==0){
        #pragma unroll
        for (int r=0;r<4;r++)
            #pragma unroll
            for (int l=0;l<LL;l++)
                out[((long)(b0+r)*TT + t)*LL + l] = acc[r][l] + bd[l];
    }
}

// ---------------- text lens ----------------
__global__ void lens_kernel(const int* __restrict__ text, float* __restrict__ outlen)
{
    __shared__ int sred[TT];
    int b = blockIdx.x, tid = threadIdx.x;
    sred[tid] = (text[b*TT+tid] != 0) ? 1 : 0;
    __syncthreads();
    for (int s=TT/2; s; s>>=1){
        if (tid < s) sred[tid] += sred[tid+s];
        __syncthreads();
    }
    if (tid==0){ g_lens[b] = sred[0]; outlen[b] = (float)sred[0]; }
}

// ---------------- fused CRF log-likelihood + Viterbi ----------------
__global__ void crf_kernel(const float* __restrict__ logits, const int* __restrict__ labels,
                           const float* __restrict__ trans, float* __restrict__ outll,
                           float* __restrict__ outtags)
{
    int b = blockIdx.x, lane = threadIdx.x;
    __shared__ float tr[LL*LL];
    __shared__ unsigned char bp[TT-1][LL];
    for (int i=lane;i<LL*LL;i+=32) tr[i]=trans[i];
    __syncwarp();
    int len = g_lens[b];
    const float* lg = logits + (long)b*TT*LL;
    const int* lab = labels + b*TT;

    float un=0.f, bi=0.f;
    for (int t=lane;t<TT;t+=32){
        if (t < len)           un += lg[t*LL + lab[t]];
        if (t >= 1 && t < len) bi += tr[lab[t-1]*LL + lab[t]];
    }
    #pragma unroll
    for (int off=16;off;off>>=1){
        un += __shfl_down_sync(0xffffffffu, un, off);
        bi += __shfl_down_sync(0xffffffffu, bi, off);
    }

    int j = (lane<LL)? lane : 0;
    float aL = (lane<LL)? lg[lane] : -1e30f;
    float aV = aL;
    for (int t=1;t<TT;t++){
        float lt = (lane<LL)? lg[t*LL+lane] : 0.f;
        float av[LL]; float mxL = -1e30f;
        float bestV = -1e30f; int bidx = 0;
        #pragma unroll
        for (int i=0;i<LL;i++){
            float aLi = __shfl_sync(0xffffffffu, aL, i);
            float aVi = __shfl_sync(0xffffffffu, aV, i);
            float trij = tr[i*LL + j];
            av[i] = aLi + trij;
            mxL = fmaxf(mxL, av[i]);
            float vV = aVi + trij;
            if (vV > bestV){ bestV = vV; bidx = i; }
        }
        float ssum = 0.f;
        #pragma unroll
        for (int i=0;i<LL;i++) ssum += __expf(av[i]-mxL);
        float nwL = __logf(ssum) + mxL + lt;
        bool m = (t < len);
        if (lane<LL){
            if (m){ aL = nwL; aV = bestV + lt; }
            bp[t-1][lane] = m ? (unsigned char)bidx : (unsigned char)lane;
        }
    }
    float mx2 = -1e30f;
    #pragma unroll
    for (int i=0;i<LL;i++) mx2 = fmaxf(mx2, __shfl_sync(0xffffffffu, aL, i));
    float s2 = 0.f;
    #pragma unroll
    for (int i=0;i<LL;i++) s2 += __expf(__shfl_sync(0xffffffffu, aL, i) - mx2);
    float log_norm = __logf(s2) + mx2;
    int last = 0; float bv = -1e30f;
    #pragma unroll
    for (int i=0;i<LL;i++){
        float v = __shfl_sync(0xffffffffu, aV, i);
        if (v > bv){ bv = v; last = i; }
    }
    if (lane==0){
        outll[b] = un + bi - log_norm;
        int tag = last;
        outtags[b*TT + TT-1] = (float)tag;
        for (int t=TT-2;t>=0;t--){
            tag = bp[t][tag];
            outtags[b*TT + t] = (float)tag;
        }
    }
}

// ---------------- launch ----------------
extern "C" void kernel_launch(void* const* d_in, const int* in_sizes, int n_in,
                              void* d_out, int out_size)
{
    const int*   text  = (const int*)  d_in[0];
    const int*   sent  = (const int*)  d_in[1];
    const int*   labels= (const int*)  d_in[2];
    const float* wemb  = (const float*)d_in[3];
    const float* semb  = (const float*)d_in[4];
    const float* Wk_f  = (const float*)d_in[5];
    const float* Wr_f  = (const float*)d_in[6];
    const float* b_f   = (const float*)d_in[7];
    const float* Wk_b  = (const float*)d_in[8];
    const float* Wr_b  = (const float*)d_in[9];
    const float* b_b   = (const float*)d_in[10];
    const float* Wd    = (const float*)d_in[11];
    const float* bd    = (const float*)d_in[12];
    const float* trans = (const float*)d_in[13];
    float* out = (float*)d_out;

    cudaFuncSetAttribute(lstm_persistent, cudaFuncAttributeMaxDynamicSharedMemorySize, LSTM_SMEM);
    cudaFuncSetAttribute(gemm_xz_kernel, cudaFuncAttributeMaxDynamicSharedMemorySize, GX_SMEM);

    // lens first so lstm_persistent is the 4th launch (ncu -s 5 captures it)
    lens_kernel<<<BB, TT>>>(text, out + LEN_OFF);
    embed_kernel<<<(MM*150 + 255)/256, 256>>>(text, sent, wemb, semb);
    gemm_xz_kernel<<<dim3(128, 32), 512, GX_SMEM>>>(Wk_f, b_f, Wk_b, b_b);
    lstm_persistent<<<128, 256, LSTM_SMEM>>>(Wr_f, Wr_b);
    logits_kernel<<<256, 512>>>(Wd, bd, out);
    crf_kernel<<<BB, 32>>>(out, labels, trans, out + LLK_OFF, out + TAG_OFF);
}